// round 4
// baseline (speedup 1.0000x reference)
#include <cuda_runtime.h>

// ---------------- problem constants ----------------
#define B_     4
#define C_     256
#define H_     128
#define W_     128
#define P_     (H_ * W_)      // 16384 pixels per batch
#define HEADS_ 8
#define BLK_   8
#define HALO_  3
#define WIN_   14
#define NKEY_  (WIN_ * WIN_)  // 196
#define NKPAD_ 224
#define NB_    256
#define KST_   36             // smem row stride (floats) for Q/K/V

// ---------------- scratch (device globals) ----------------
__device__ float g_qkv[(size_t)B_ * P_ * 768];   // [b][p][o]  q|k|v
__device__ float g_ctx[(size_t)B_ * P_ * C_];    // [b][p][c]  pixel-major

// =====================================================================
// Kernel 1: QKV projection, ping-pong double buffered.
// out[p][o] = sum_c x[c][p] * W[o][c]. BM=128(p) BN=128(o) BK=16, 256thr.
// =====================================================================
__global__ __launch_bounds__(256) void qkv_gemm_k(
    const float* __restrict__ x,
    const float* __restrict__ wq,
    const float* __restrict__ wkv)
{
    __shared__ float As[2][16][128];
    __shared__ float Bs[2][16][128];

    const int pT  = blockIdx.x * 128;
    const int oT  = blockIdx.y * 128;
    const int b   = blockIdx.z;
    const int tid = threadIdx.x;
    const int m0  = (tid >> 4) * 4;
    const int n0  = (tid & 15) * 4;

    const float* xb = x + (size_t)b * C_ * P_;

    const int ka0 = tid >> 5;
    const int ma4 = (tid & 31) << 2;
    const int ol0 = tid >> 2;
    const int ol1 = ol0 + 64;
    const int k4  = (tid & 3) << 2;
    const int or0 = oT + ol0;
    const int or1 = oT + ol1;
    const float* wr0 = (or0 < 256) ? (wq + or0 * 256) : (wkv + (or0 - 256) * 256);
    const float* wr1 = (or1 < 256) ? (wq + or1 * 256) : (wkv + (or1 - 256) * 256);

    float acc[8][8];
#pragma unroll
    for (int i = 0; i < 8; i++)
#pragma unroll
        for (int j = 0; j < 8; j++) acc[i][j] = 0.f;

    float4 ra0, ra1, rb0, rb1;

#define QKV_LOADG(K0)                                                          \
    {                                                                          \
        ra0 = *(const float4*)&xb[(size_t)((K0) + ka0) * P_ + pT + ma4];       \
        ra1 = *(const float4*)&xb[(size_t)((K0) + 8 + ka0) * P_ + pT + ma4];   \
        rb0 = *(const float4*)&wr0[(K0) + k4];                                 \
        rb1 = *(const float4*)&wr1[(K0) + k4];                                 \
    }
#define QKV_STORE(BUF)                                                         \
    {                                                                          \
        *(float4*)&As[BUF][ka0][ma4]     = ra0;                                \
        *(float4*)&As[BUF][8 + ka0][ma4] = ra1;                                \
        Bs[BUF][k4 + 0][ol0] = rb0.x; Bs[BUF][k4 + 1][ol0] = rb0.y;            \
        Bs[BUF][k4 + 2][ol0] = rb0.z; Bs[BUF][k4 + 3][ol0] = rb0.w;            \
        Bs[BUF][k4 + 0][ol1] = rb1.x; Bs[BUF][k4 + 1][ol1] = rb1.y;            \
        Bs[BUF][k4 + 2][ol1] = rb1.z; Bs[BUF][k4 + 3][ol1] = rb1.w;            \
    }

    QKV_LOADG(0);
    QKV_STORE(0);
    __syncthreads();

    for (int it = 0; it < 16; it++) {
        const int buf = it & 1;
        if (it < 15) QKV_LOADG((it + 1) * 16);
#pragma unroll
        for (int kk = 0; kk < 16; kk++) {
            float4 a0 = *(float4*)&As[buf][kk][m0];
            float4 a1 = *(float4*)&As[buf][kk][m0 + 64];
            float4 b0 = *(float4*)&Bs[buf][kk][n0];
            float4 b1 = *(float4*)&Bs[buf][kk][n0 + 64];
            float a[8] = {a0.x, a0.y, a0.z, a0.w, a1.x, a1.y, a1.z, a1.w};
            float bb[8] = {b0.x, b0.y, b0.z, b0.w, b1.x, b1.y, b1.z, b1.w};
#pragma unroll
            for (int i = 0; i < 8; i++)
#pragma unroll
                for (int j = 0; j < 8; j++) acc[i][j] += a[i] * bb[j];
        }
        if (it < 15) {
            QKV_STORE(buf ^ 1);
            __syncthreads();
        }
    }

#pragma unroll
    for (int i = 0; i < 8; i++) {
        int m = (i < 4) ? (m0 + i) : (m0 + 64 + (i - 4));
        float* orow = &g_qkv[((size_t)b * P_ + pT + m) * 768 + oT];
        *(float4*)&orow[n0]      = make_float4(acc[i][0], acc[i][1], acc[i][2], acc[i][3]);
        *(float4*)&orow[n0 + 64] = make_float4(acc[i][4], acc[i][5], acc[i][6], acc[i][7]);
    }
}

// =====================================================================
// Kernel 2: halo attention. One CTA per (batch, block, q-half).
// 256 threads, 32 queries per CTA, smem ~101KB -> 2 CTAs/SM.
// =====================================================================
// smem layout (floats)
#define OQ_   0                                 // 32*36   = 1152
#define OK_   (OQ_ + 32 * KST_)                 // 224*36  = 8064
#define OV_   (OK_ + NKPAD_ * KST_)             // 196*36  = 7056
#define OS_   (OV_ + 196 * KST_)                // 32*197  = 6304
#define OBW_  (OS_ + 32 * 197)                  // 448
#define OBH_  (OBW_ + 448)                      // 448
#define ORH_  (OBH_ + 448)                      // 864
#define ORW_  (ORH_ + 864)                      // 864
#define SMEMF_ (ORW_ + 864)                     // 25200 floats = 100800 B

__global__ __launch_bounds__(256) void halo_attn_k(
    const float* __restrict__ rel_h,
    const float* __restrict__ rel_w)
{
    extern __shared__ float sm[];
    float* sQ  = sm + OQ_;
    float* sK  = sm + OK_;
    float* sV  = sm + OV_;
    float* sS  = sm + OS_;
    float* sBW = sm + OBW_;
    float* sBH = sm + OBH_;
    float* sRH = sm + ORH_;
    float* sRW = sm + ORW_;

    const int b     = blockIdx.y;
    const int blk   = blockIdx.x >> 1;
    const int half  = blockIdx.x & 1;
    const int qbase = half * 32;
    const int bh    = blk >> 4;
    const int bw    = blk & 15;
    const int tid   = threadIdx.x;
    const int w     = tid >> 5;
    const int lane  = tid & 31;
    const float scale = 0.1767766952966369f;  // 1/sqrt(32)

    // rel tables + zero K pad rows (once)
    for (int i = tid; i < 27 * 32; i += 256) {
        sRH[i] = rel_h[i];
        sRW[i] = rel_w[i];
    }
    for (int i = tid; i < (NKPAD_ - NKEY_) * KST_; i += 256)
        sK[NKEY_ * KST_ + i] = 0.f;

    for (int hd = 0; hd < HEADS_; hd++) {
        __syncthreads();  // protects smem reuse across heads (and init)

        // ---- load Q: 32 rows x 32 (one float4 per thread) ----
        {
            int r = tid >> 3, d4 = (tid & 7) << 2;
            int qi = qbase + r;
            int p = (bh * 8 + (qi >> 3)) * 128 + bw * 8 + (qi & 7);
            float4 v = *(const float4*)&g_qkv[((size_t)b * P_ + p) * 768 + hd * 32 + d4];
            *(float4*)&sQ[r * KST_ + d4] = v;
        }
        // ---- load K,V: 196 rows x 32 each (float4, zero-pad halo) ----
        for (int idx = tid; idx < NKEY_ * 16; idx += 256) {
            int r = idx >> 4, rem = idx & 15;
            int arr = rem >> 3, d4 = (rem & 7) << 2;
            int iw = r / 14, jw = r - iw * 14;
            int hp = bh * 8 - HALO_ + iw;
            int wp = bw * 8 - HALO_ + jw;
            float4 v = make_float4(0.f, 0.f, 0.f, 0.f);
            if (hp >= 0 && hp < H_ && wp >= 0 && wp < W_)
                v = *(const float4*)&g_qkv[((size_t)b * P_ + hp * 128 + wp) * 768
                                           + 256 + arr * 256 + hd * 32 + d4];
            float* dst = arr ? sV : sK;
            *(float4*)&dst[r * KST_ + d4] = v;
        }
        __syncthreads();

        // ---- rel-pos bias (32 q x 14) ----
        for (int idx = tid; idx < 32 * 14; idx += 256) {
            int ql = idx / 14, j = idx - ql * 14;
            int qi = qbase + ql;
            int xq = qi >> 3, yq = qi & 7;
            const float4* qr = (const float4*)(sQ + ql * KST_);
            const float4* rw = (const float4*)(sRW + (j - yq + 13) * 32);
            const float4* rh = (const float4*)(sRH + (j - xq + 13) * 32);
            float aw = 0.f, ah = 0.f;
#pragma unroll
            for (int d = 0; d < 8; d++) {
                float4 q = qr[d], a = rw[d], c = rh[d];
                aw += q.x * a.x + q.y * a.y + q.z * a.z + q.w * a.w;
                ah += q.x * c.x + q.y * c.y + q.z * c.z + q.w * c.w;
            }
            sBW[idx] = aw;
            sBH[idx] = ah;
        }
        __syncthreads();

        // ---- scores: 4q x 7k per thread ----
        {
            const int q0 = (w >> 2) * 16 + (lane >> 3) * 4;   // 0..28
            const int k0 = (w & 3) * 56 + (lane & 7) * 7;     // 0..217
            float acc[4][7];
#pragma unroll
            for (int i = 0; i < 4; i++)
#pragma unroll
                for (int j = 0; j < 7; j++) acc[i][j] = 0.f;

#pragma unroll
            for (int ds = 0; ds < 8; ds++) {
                int d = ds * 4;
                float4 qv[4], kv[7];
#pragma unroll
                for (int i = 0; i < 4; i++) qv[i] = *(float4*)&sQ[(q0 + i) * KST_ + d];
#pragma unroll
                for (int j = 0; j < 7; j++) kv[j] = *(float4*)&sK[(k0 + j) * KST_ + d];
#pragma unroll
                for (int i = 0; i < 4; i++)
#pragma unroll
                    for (int j = 0; j < 7; j++)
                        acc[i][j] += qv[i].x * kv[j].x + qv[i].y * kv[j].y
                                   + qv[i].z * kv[j].z + qv[i].w * kv[j].w;
            }
#pragma unroll
            for (int i = 0; i < 4; i++) {
                int qi = q0 + i;
#pragma unroll
                for (int j = 0; j < 7; j++) {
                    int kj = k0 + j;
                    if (kj < NKEY_) {
                        int r14 = kj / 14;
                        int c14 = kj - r14 * 14;
                        sS[qi * 197 + kj] = acc[i][j] * scale
                                          + sBW[qi * 14 + c14]
                                          + sBH[qi * 14 + r14];
                    }
                }
            }
        }
        __syncthreads();

        // ---- softmax per row (8 warps x 4 rows) ----
        for (int r = w * 4; r < w * 4 + 4; r++) {
            float* row = sS + r * 197;
            float m = -1e30f;
            for (int c = lane; c < NKEY_; c += 32) m = fmaxf(m, row[c]);
#pragma unroll
            for (int o = 16; o; o >>= 1) m = fmaxf(m, __shfl_xor_sync(0xffffffffu, m, o));
            float s = 0.f;
            for (int c = lane; c < NKEY_; c += 32) {
                float e = __expf(row[c] - m);
                row[c] = e;
                s += e;
            }
#pragma unroll
            for (int o = 16; o; o >>= 1) s += __shfl_xor_sync(0xffffffffu, s, o);
            float inv = 1.f / s;
            for (int c = lane; c < NKEY_; c += 32) row[c] *= inv;
        }
        __syncthreads();

        // ---- ctx: 1q x 4d per thread over all 196 keys; coalesced store ----
        {
            const int q  = tid >> 3;          // 0..31
            const int d0 = (tid & 7) * 4;     // 0..28
            float ax = 0.f, ay = 0.f, az = 0.f, aw = 0.f;
            const float* sp = sS + q * 197;
            const float* vp = sV + d0;
#pragma unroll 4
            for (int k = 0; k < NKEY_; k++) {
                float s = sp[k];
                float4 v = *(float4*)&vp[k * KST_];
                ax += s * v.x; ay += s * v.y; az += s * v.z; aw += s * v.w;
            }
            int qi = qbase + q;
            int p = (bh * 8 + (qi >> 3)) * 128 + bw * 8 + (qi & 7);
            *(float4*)&g_ctx[((size_t)b * P_ + p) * C_ + hd * 32 + d0] =
                make_float4(ax, ay, az, aw);
        }
    }
}

// =====================================================================
// Kernel 3: FC epilogue, ping-pong, reads pixel-major ctx.
// out[b][o][p] = fc_w[o][:]·ctx[b][p][:] + b[o]
// BM=64 (o), BN=128 (p), BK=16, 256 threads, 4x8 microtile.
// =====================================================================
#define BSTRIDE_ 132

__global__ __launch_bounds__(256) void fc_gemm_k(
    const float* __restrict__ fcw,
    const float* __restrict__ fcb,
    float* __restrict__ out)
{
    __shared__ float As[2][16][64];
    __shared__ float Bs[2][16][BSTRIDE_];

    const int pT  = blockIdx.x * 128;
    const int oT  = blockIdx.y * 64;
    const int b   = blockIdx.z;
    const int tid = threadIdx.x;
    const int m0  = (tid >> 4) * 4;
    const int n0  = (tid & 15) * 4;

    const int am = tid & 63;
    const int ak = (tid >> 6) * 4;
    const int pl = tid >> 1;          // 0..127
    const int cg = (tid & 1) * 4;     // 0 or 4
    const float* arow = fcw + (oT + am) * 256;
    const float* ctxb = g_ctx + ((size_t)b * P_ + pT) * C_;

    float acc[4][8];
#pragma unroll
    for (int i = 0; i < 4; i++)
#pragma unroll
        for (int j = 0; j < 8; j++) acc[i][j] = 0.f;

    float4 ra, rb0, rb1;

#define FC_LOADG(K0)                                                           \
    {                                                                          \
        ra  = *(const float4*)&arow[(K0) + ak];                                \
        rb0 = *(const float4*)&ctxb[(size_t)pl * C_ + (K0) + cg];              \
        rb1 = *(const float4*)&ctxb[(size_t)pl * C_ + (K0) + 8 + cg];          \
    }
#define FC_STORE(BUF)                                                          \
    {                                                                          \
        As[BUF][ak + 0][am] = ra.x; As[BUF][ak + 1][am] = ra.y;                \
        As[BUF][ak + 2][am] = ra.z; As[BUF][ak + 3][am] = ra.w;                \
        Bs[BUF][cg + 0][pl] = rb0.x; Bs[BUF][cg + 1][pl] = rb0.y;              \
        Bs[BUF][cg + 2][pl] = rb0.z; Bs[BUF][cg + 3][pl] = rb0.w;              \
        Bs[BUF][8 + cg + 0][pl] = rb1.x; Bs[BUF][8 + cg + 1][pl] = rb1.y;      \
        Bs[BUF][8 + cg + 2][pl] = rb1.z; Bs[BUF][8 + cg + 3][pl] = rb1.w;      \
    }

    FC_LOADG(0);
    FC_STORE(0);
    __syncthreads();

    for (int it = 0; it < 16; it++) {
        const int buf = it & 1;
        if (it < 15) FC_LOADG((it + 1) * 16);
#pragma unroll
        for (int kk = 0; kk < 16; kk++) {
            float4 av = *(float4*)&As[buf][kk][m0];
            float4 b0 = *(float4*)&Bs[buf][kk][n0];
            float4 b1 = *(float4*)&Bs[buf][kk][n0 + 64];
            float a[4] = {av.x, av.y, av.z, av.w};
            float bb[8] = {b0.x, b0.y, b0.z, b0.w, b1.x, b1.y, b1.z, b1.w};
#pragma unroll
            for (int i = 0; i < 4; i++)
#pragma unroll
                for (int j = 0; j < 8; j++) acc[i][j] += a[i] * bb[j];
        }
        if (it < 15) {
            FC_STORE(buf ^ 1);
            __syncthreads();
        }
    }

#pragma unroll
    for (int i = 0; i < 4; i++) {
        int o = oT + m0 + i;
        float bias = fcb[o];
        float* orow = out + ((size_t)b * C_ + o) * P_ + pT;
        *(float4*)&orow[n0]      = make_float4(acc[i][0] + bias, acc[i][1] + bias,
                                               acc[i][2] + bias, acc[i][3] + bias);
        *(float4*)&orow[n0 + 64] = make_float4(acc[i][4] + bias, acc[i][5] + bias,
                                               acc[i][6] + bias, acc[i][7] + bias);
    }
}

// =====================================================================
extern "C" void kernel_launch(void* const* d_in, const int* in_sizes, int n_in,
                              void* d_out, int out_size)
{
    const float* x   = (const float*)d_in[0];
    const float* wq  = (const float*)d_in[1];
    const float* wkv = (const float*)d_in[2];
    const float* fcw = (const float*)d_in[3];
    const float* fcb = (const float*)d_in[4];
    const float* rh  = (const float*)d_in[5];
    const float* rw  = (const float*)d_in[6];
    float* out = (float*)d_out;

    cudaFuncSetAttribute(halo_attn_k,
                         cudaFuncAttributeMaxDynamicSharedMemorySize,
                         SMEMF_ * (int)sizeof(float));

    qkv_gemm_k<<<dim3(P_ / 128, 6, B_), 256>>>(x, wq, wkv);
    halo_attn_k<<<dim3(NB_ * 2, B_), 256, SMEMF_ * sizeof(float)>>>(rh, rw);
    fc_gemm_k<<<dim3(P_ / 128, C_ / 64, B_), 256>>>(fcw, fcb, out);
}

// round 6
// speedup vs baseline: 1.1248x; 1.1248x over previous
#include <cuda_runtime.h>
#include <cuda_fp16.h>

// ---------------- problem constants ----------------
#define B_     4
#define C_     256
#define H_     128
#define W_     128
#define P_     (H_ * W_)      // 16384 pixels per batch
#define HEADS_ 8
#define BLK_   8
#define HALO_  3
#define WIN_   14
#define NKEY_  (WIN_ * WIN_)  // 196
#define NKPAD_ 224
#define NB_    256
#define KST_   36             // smem row stride (floats) for Q/K/V

// ---------------- scratch (device globals) ----------------
__device__ float g_qkv[(size_t)B_ * P_ * 768];   // [b][p][o]  q|k|v
__device__ float g_ctx[(size_t)B_ * P_ * C_];    // [b][p][c]  pixel-major

// =====================================================================
// Kernel 1: QKV projection, ping-pong double buffered.
// =====================================================================
__global__ __launch_bounds__(256) void qkv_gemm_k(
    const float* __restrict__ x,
    const float* __restrict__ wq,
    const float* __restrict__ wkv)
{
    __shared__ float As[2][16][128];
    __shared__ float Bs[2][16][128];

    const int pT  = blockIdx.x * 128;
    const int oT  = blockIdx.y * 128;
    const int b   = blockIdx.z;
    const int tid = threadIdx.x;
    const int m0  = (tid >> 4) * 4;
    const int n0  = (tid & 15) * 4;

    const float* xb = x + (size_t)b * C_ * P_;

    const int ka0 = tid >> 5;
    const int ma4 = (tid & 31) << 2;
    const int ol0 = tid >> 2;
    const int ol1 = ol0 + 64;
    const int k4  = (tid & 3) << 2;
    const int or0 = oT + ol0;
    const int or1 = oT + ol1;
    const float* wr0 = (or0 < 256) ? (wq + or0 * 256) : (wkv + (or0 - 256) * 256);
    const float* wr1 = (or1 < 256) ? (wq + or1 * 256) : (wkv + (or1 - 256) * 256);

    float acc[8][8];
#pragma unroll
    for (int i = 0; i < 8; i++)
#pragma unroll
        for (int j = 0; j < 8; j++) acc[i][j] = 0.f;

    float4 ra0, ra1, rb0, rb1;

#define QKV_LOADG(K0)                                                          \
    {                                                                          \
        ra0 = *(const float4*)&xb[(size_t)((K0) + ka0) * P_ + pT + ma4];       \
        ra1 = *(const float4*)&xb[(size_t)((K0) + 8 + ka0) * P_ + pT + ma4];   \
        rb0 = *(const float4*)&wr0[(K0) + k4];                                 \
        rb1 = *(const float4*)&wr1[(K0) + k4];                                 \
    }
#define QKV_STORE(BUF)                                                         \
    {                                                                          \
        *(float4*)&As[BUF][ka0][ma4]     = ra0;                                \
        *(float4*)&As[BUF][8 + ka0][ma4] = ra1;                                \
        Bs[BUF][k4 + 0][ol0] = rb0.x; Bs[BUF][k4 + 1][ol0] = rb0.y;            \
        Bs[BUF][k4 + 2][ol0] = rb0.z; Bs[BUF][k4 + 3][ol0] = rb0.w;            \
        Bs[BUF][k4 + 0][ol1] = rb1.x; Bs[BUF][k4 + 1][ol1] = rb1.y;            \
        Bs[BUF][k4 + 2][ol1] = rb1.z; Bs[BUF][k4 + 3][ol1] = rb1.w;            \
    }

    QKV_LOADG(0);
    QKV_STORE(0);
    __syncthreads();

    for (int it = 0; it < 16; it++) {
        const int buf = it & 1;
        if (it < 15) QKV_LOADG((it + 1) * 16);
#pragma unroll
        for (int kk = 0; kk < 16; kk++) {
            float4 a0 = *(float4*)&As[buf][kk][m0];
            float4 a1 = *(float4*)&As[buf][kk][m0 + 64];
            float4 b0 = *(float4*)&Bs[buf][kk][n0];
            float4 b1 = *(float4*)&Bs[buf][kk][n0 + 64];
            float a[8] = {a0.x, a0.y, a0.z, a0.w, a1.x, a1.y, a1.z, a1.w};
            float bb[8] = {b0.x, b0.y, b0.z, b0.w, b1.x, b1.y, b1.z, b1.w};
#pragma unroll
            for (int i = 0; i < 8; i++)
#pragma unroll
                for (int j = 0; j < 8; j++) acc[i][j] += a[i] * bb[j];
        }
        if (it < 15) {
            QKV_STORE(buf ^ 1);
            __syncthreads();
        }
    }

#pragma unroll
    for (int i = 0; i < 8; i++) {
        int m = (i < 4) ? (m0 + i) : (m0 + 64 + (i - 4));
        float* orow = &g_qkv[((size_t)b * P_ + pT + m) * 768 + oT];
        *(float4*)&orow[n0]      = make_float4(acc[i][0], acc[i][1], acc[i][2], acc[i][3]);
        *(float4*)&orow[n0 + 64] = make_float4(acc[i][4], acc[i][5], acc[i][6], acc[i][7]);
    }
}

// =====================================================================
// Kernel 2: halo attention. 64 queries/CTA, 512 threads, scores in regs,
// fp16 probabilities, smem 111.4KB -> 2 CTAs/SM (regs capped at 64).
// =====================================================================
// smem layout (float units)
#define OQ_   0                                 // 64*36   = 2304
#define OK_   (OQ_ + 64 * KST_)                 // 224*36  = 8064
#define OV_   (OK_ + NKPAD_ * KST_)             // 196*36  = 7056
#define OP_   (OV_ + 196 * KST_)                // 64*200 half = 6400 fl
#define OM_   (OP_ + 6400)                      // 256
#define OL_   (OM_ + 256)                       // 256
#define OBW_  (OL_ + 256)                       // 896
#define OBH_  (OBW_ + 896)                      // 896
#define ORH_  (OBH_ + 896)                      // 864
#define ORW_  (ORH_ + 864)                      // 864
#define SMEMF_ (ORW_ + 864)                     // 27856 fl = 111424 B

__global__ __launch_bounds__(512, 2) void halo_attn_k(
    const float* __restrict__ rel_h,
    const float* __restrict__ rel_w)
{
    extern __shared__ float sm[];
    float*  sQ  = sm + OQ_;
    float*  sK  = sm + OK_;
    float*  sV  = sm + OV_;
    __half* sP  = (__half*)(sm + OP_);
    float*  sM  = sm + OM_;
    float*  sL  = sm + OL_;
    float*  sBW = sm + OBW_;
    float*  sBH = sm + OBH_;
    float*  sRH = sm + ORH_;
    float*  sRW = sm + ORW_;

    const int b    = blockIdx.y;
    const int blk  = blockIdx.x;
    const int bh   = blk >> 4;
    const int bw   = blk & 15;
    const int tid  = threadIdx.x;
    const int w    = tid >> 5;
    const int lane = tid & 31;
    const int qg   = lane >> 3;        // 0..3
    const int kg   = lane & 7;         // 0..7
    const int qt   = (w >> 2) * 16 + qg * 4;   // base q row (0..60)
    const int kt   = w & 3;                    // k tile
    const int k0   = kt * 56 + kg * 7;         // base key (0..217)
    const float scale = 0.1767766952966369f;   // 1/sqrt(32)

    // rel tables + zero K pad rows (once)
    for (int i = tid; i < 27 * 32; i += 512) {
        sRH[i] = rel_h[i];
        sRW[i] = rel_w[i];
    }
    for (int i = tid; i < (NKPAD_ - NKEY_) * KST_; i += 512)
        sK[NKEY_ * KST_ + i] = 0.f;

    // incremental kj -> (row, col) base for this thread's 7 keys
    const int r14b = k0 / 14;
    const int c14b = k0 - r14b * 14;

    for (int hd = 0; hd < HEADS_; hd++) {
        __syncthreads();  // smem reuse guard across heads (and init)

        // ---- load Q: 64 rows x 32 ----
        {
            int r = tid >> 3, d4 = (tid & 7) << 2;
            int p = (bh * 8 + (r >> 3)) * 128 + bw * 8 + (r & 7);
            float4 v = *(const float4*)&g_qkv[((size_t)b * P_ + p) * 768 + hd * 32 + d4];
            *(float4*)&sQ[r * KST_ + d4] = v;
        }
        // ---- load K,V: 196 rows x 32 each (zero-pad halo) ----
        for (int idx = tid; idx < NKEY_ * 16; idx += 512) {
            int r = idx >> 4, rem = idx & 15;
            int arr = rem >> 3, d4 = (rem & 7) << 2;
            int iw = r / 14, jw = r - iw * 14;
            int hp = bh * 8 - HALO_ + iw;
            int wp = bw * 8 - HALO_ + jw;
            float4 v = make_float4(0.f, 0.f, 0.f, 0.f);
            if (hp >= 0 && hp < H_ && wp >= 0 && wp < W_)
                v = *(const float4*)&g_qkv[((size_t)b * P_ + hp * 128 + wp) * 768
                                           + 256 + arr * 256 + hd * 32 + d4];
            float* dst = arr ? sV : sK;
            *(float4*)&dst[r * KST_ + d4] = v;
        }
        __syncthreads();

        // ---- rel-pos bias ----
        for (int idx = tid; idx < 64 * 14; idx += 512) {
            int qi = idx / 14, j = idx - qi * 14;
            int xq = qi >> 3, yq = qi & 7;
            const float4* qr = (const float4*)(sQ + qi * KST_);
            const float4* rw = (const float4*)(sRW + (j - yq + 13) * 32);
            const float4* rh = (const float4*)(sRH + (j - xq + 13) * 32);
            float aw = 0.f, ah = 0.f;
#pragma unroll 2
            for (int d = 0; d < 8; d++) {
                float4 q = qr[d], a = rw[d], c = rh[d];
                aw += q.x * a.x + q.y * a.y + q.z * a.z + q.w * a.w;
                ah += q.x * c.x + q.y * c.y + q.z * c.z + q.w * c.w;
            }
            sBW[idx] = aw;
            sBH[idx] = ah;
        }
        __syncthreads();

        // ---- scores in registers: 4q x 7k per thread ----
        float acc[4][7];
#pragma unroll
        for (int i = 0; i < 4; i++)
#pragma unroll
            for (int j = 0; j < 7; j++) acc[i][j] = 0.f;

        for (int ds = 0; ds < 8; ds++) {
            const int d = ds * 4;
            float4 qv[4];
#pragma unroll
            for (int i = 0; i < 4; i++) qv[i] = *(float4*)&sQ[(qt + i) * KST_ + d];
#pragma unroll
            for (int j = 0; j < 7; j++) {
                float4 kv = *(float4*)&sK[(k0 + j) * KST_ + d];
#pragma unroll
                for (int i = 0; i < 4; i++)
                    acc[i][j] += qv[i].x * kv.x + qv[i].y * kv.y
                               + qv[i].z * kv.z + qv[i].w * kv.w;
            }
        }

        // ---- epilogue (scale+bias) + per-thread max ----
        float lmax[4] = {-1e30f, -1e30f, -1e30f, -1e30f};
        {
            int rr = r14b, cc = c14b;
#pragma unroll
            for (int j = 0; j < 7; j++) {
                const int kj = k0 + j;
                const bool val = (kj < NKEY_);
#pragma unroll
                for (int i = 0; i < 4; i++) {
                    float s = acc[i][j] * scale
                            + sBW[(qt + i) * 14 + cc]
                            + sBH[(qt + i) * 14 + rr];
                    acc[i][j] = s;
                    if (val) lmax[i] = fmaxf(lmax[i], s);
                }
                cc++;
                if (cc == 14) { cc = 0; rr++; }
            }
        }
        // reduce max over the 8 k-lanes of this q-group
#pragma unroll
        for (int i = 0; i < 4; i++) {
#pragma unroll
            for (int o = 1; o < 8; o <<= 1)
                lmax[i] = fmaxf(lmax[i], __shfl_xor_sync(0xffffffffu, lmax[i], o));
        }
        if (kg == 0) {
#pragma unroll
            for (int i = 0; i < 4; i++) sM[(qt + i) * 4 + kt] = lmax[i];
        }
        __syncthreads();

        // ---- exp + partial sums + fp16 prob store ----
        float lsum[4] = {0.f, 0.f, 0.f, 0.f};
        {
            float m[4];
#pragma unroll
            for (int i = 0; i < 4; i++) {
                const float* mp = sM + (qt + i) * 4;
                m[i] = fmaxf(fmaxf(mp[0], mp[1]), fmaxf(mp[2], mp[3]));
            }
#pragma unroll
            for (int j = 0; j < 7; j++) {
                const int kj = k0 + j;
                if (kj < NKEY_) {
#pragma unroll
                    for (int i = 0; i < 4; i++) {
                        float e = __expf(acc[i][j] - m[i]);
                        lsum[i] += e;
                        sP[(qt + i) * 200 + kj] = __float2half_rn(e);
                    }
                }
            }
        }
#pragma unroll
        for (int i = 0; i < 4; i++) {
#pragma unroll
            for (int o = 1; o < 8; o <<= 1)
                lsum[i] += __shfl_xor_sync(0xffffffffu, lsum[i], o);
        }
        if (kg == 0) {
#pragma unroll
            for (int i = 0; i < 4; i++) sL[(qt + i) * 4 + kt] = lsum[i];
        }
        __syncthreads();

        // ---- ctx: 1q x 4d per thread; normalize at the end ----
        {
            const int q  = tid >> 3;          // 0..63
            const int d0 = (tid & 7) * 4;     // 0..28
            const float* lp = sL + q * 4;
            const float invl = 1.f / (lp[0] + lp[1] + lp[2] + lp[3]);
            float ax = 0.f, ay = 0.f, az = 0.f, aw = 0.f;
            const __half2* sp2 = (const __half2*)(sP + q * 200);
            const float* vp = sV + d0;
#pragma unroll 2
            for (int k2 = 0; k2 < NKEY_ / 2; k2++) {
                float2 ss = __half22float2(sp2[k2]);
                float4 v0 = *(float4*)&vp[(2 * k2) * KST_];
                float4 v1 = *(float4*)&vp[(2 * k2 + 1) * KST_];
                ax += ss.x * v0.x + ss.y * v1.x;
                ay += ss.x * v0.y + ss.y * v1.y;
                az += ss.x * v0.z + ss.y * v1.z;
                aw += ss.x * v0.w + ss.y * v1.w;
            }
            int p = (bh * 8 + (q >> 3)) * 128 + bw * 8 + (q & 7);
            *(float4*)&g_ctx[((size_t)b * P_ + p) * C_ + hd * 32 + d0] =
                make_float4(ax * invl, ay * invl, az * invl, aw * invl);
        }
    }
}

// =====================================================================
// Kernel 3: FC epilogue, ping-pong, reads pixel-major ctx.
// =====================================================================
#define BSTRIDE_ 132

__global__ __launch_bounds__(256) void fc_gemm_k(
    const float* __restrict__ fcw,
    const float* __restrict__ fcb,
    float* __restrict__ out)
{
    __shared__ float As[2][16][64];
    __shared__ float Bs[2][16][BSTRIDE_];

    const int pT  = blockIdx.x * 128;
    const int oT  = blockIdx.y * 64;
    const int b   = blockIdx.z;
    const int tid = threadIdx.x;
    const int m0  = (tid >> 4) * 4;
    const int n0  = (tid & 15) * 4;

    const int am = tid & 63;
    const int ak = (tid >> 6) * 4;
    const int pl = tid >> 1;
    const int cg = (tid & 1) * 4;
    const float* arow = fcw + (oT + am) * 256;
    const float* ctxb = g_ctx + ((size_t)b * P_ + pT) * C_;

    float acc[4][8];
#pragma unroll
    for (int i = 0; i < 4; i++)
#pragma unroll
        for (int j = 0; j < 8; j++) acc[i][j] = 0.f;

    float4 ra, rb0, rb1;

#define FC_LOADG(K0)                                                           \
    {                                                                          \
        ra  = *(const float4*)&arow[(K0) + ak];                                \
        rb0 = *(const float4*)&ctxb[(size_t)pl * C_ + (K0) + cg];              \
        rb1 = *(const float4*)&ctxb[(size_t)pl * C_ + (K0) + 8 + cg];          \
    }
#define FC_STORE(BUF)                                                          \
    {                                                                          \
        As[BUF][ak + 0][am] = ra.x; As[BUF][ak + 1][am] = ra.y;                \
        As[BUF][ak + 2][am] = ra.z; As[BUF][ak + 3][am] = ra.w;                \
        Bs[BUF][cg + 0][pl] = rb0.x; Bs[BUF][cg + 1][pl] = rb0.y;              \
        Bs[BUF][cg + 2][pl] = rb0.z; Bs[BUF][cg + 3][pl] = rb0.w;              \
        Bs[BUF][8 + cg + 0][pl] = rb1.x; Bs[BUF][8 + cg + 1][pl] = rb1.y;      \
        Bs[BUF][8 + cg + 2][pl] = rb1.z; Bs[BUF][8 + cg + 3][pl] = rb1.w;      \
    }

    FC_LOADG(0);
    FC_STORE(0);
    __syncthreads();

    for (int it = 0; it < 16; it++) {
        const int buf = it & 1;
        if (it < 15) FC_LOADG((it + 1) * 16);
#pragma unroll
        for (int kk = 0; kk < 16; kk++) {
            float4 av = *(float4*)&As[buf][kk][m0];
            float4 b0 = *(float4*)&Bs[buf][kk][n0];
            float4 b1 = *(float4*)&Bs[buf][kk][n0 + 64];
            float a[4] = {av.x, av.y, av.z, av.w};
            float bb[8] = {b0.x, b0.y, b0.z, b0.w, b1.x, b1.y, b1.z, b1.w};
#pragma unroll
            for (int i = 0; i < 4; i++)
#pragma unroll
                for (int j = 0; j < 8; j++) acc[i][j] += a[i] * bb[j];
        }
        if (it < 15) {
            FC_STORE(buf ^ 1);
            __syncthreads();
        }
    }

#pragma unroll
    for (int i = 0; i < 4; i++) {
        int o = oT + m0 + i;
        float bias = fcb[o];
        float* orow = out + ((size_t)b * C_ + o) * P_ + pT;
        *(float4*)&orow[n0]      = make_float4(acc[i][0] + bias, acc[i][1] + bias,
                                               acc[i][2] + bias, acc[i][3] + bias);
        *(float4*)&orow[n0 + 64] = make_float4(acc[i][4] + bias, acc[i][5] + bias,
                                               acc[i][6] + bias, acc[i][7] + bias);
    }
}

// =====================================================================
extern "C" void kernel_launch(void* const* d_in, const int* in_sizes, int n_in,
                              void* d_out, int out_size)
{
    const float* x   = (const float*)d_in[0];
    const float* wq  = (const float*)d_in[1];
    const float* wkv = (const float*)d_in[2];
    const float* fcw = (const float*)d_in[3];
    const float* fcb = (const float*)d_in[4];
    const float* rh  = (const float*)d_in[5];
    const float* rw  = (const float*)d_in[6];
    float* out = (float*)d_out;

    cudaFuncSetAttribute(halo_attn_k,
                         cudaFuncAttributeMaxDynamicSharedMemorySize,
                         SMEMF_ * (int)sizeof(float));

    qkv_gemm_k<<<dim3(P_ / 128, 6, B_), 256>>>(x, wq, wkv);
    halo_attn_k<<<dim3(NB_, B_), 512, SMEMF_ * sizeof(float)>>>(rh, rw);
    fc_gemm_k<<<dim3(P_ / 128, C_ / 64, B_), 256>>>(fcw, fcb, out);
}

// round 11
// speedup vs baseline: 1.1403x; 1.0138x over previous
#include <cuda_runtime.h>
#include <cuda_fp16.h>

// ---------------- problem constants ----------------
#define B_     4
#define C_     256
#define H_     128
#define W_     128
#define P_     (H_ * W_)      // 16384 pixels per batch
#define HEADS_ 8
#define BLK_   8
#define HALO_  3
#define WIN_   14
#define NKEY_  (WIN_ * WIN_)  // 196
#define NKPAD_ 224
#define NB_    256
#define KST_   36             // smem row stride (floats) for Q/K/V
#define ROWF_  512            // g_qkv row: q 256 f32 | k 256 f16 | v 256 f16

// ---------------- scratch (device globals) ----------------
__device__ float g_qkv[(size_t)B_ * P_ * ROWF_];  // [b][p]: q f32 | k f16 | v f16
__device__ float g_ctx[(size_t)B_ * P_ * C_];     // [b][p][c] pixel-major

// =====================================================================
// Kernel 1: QKV projection, ping-pong double buffered.
// out[p][o] = sum_c x[c][p] * W[o][c]; k/v ranges stored fp16.
// =====================================================================
__global__ __launch_bounds__(256) void qkv_gemm_k(
    const float* __restrict__ x,
    const float* __restrict__ wq,
    const float* __restrict__ wkv)
{
    __shared__ float As[2][16][128];
    __shared__ float Bs[2][16][128];

    const int pT  = blockIdx.x * 128;
    const int oT  = blockIdx.y * 128;
    const int b   = blockIdx.z;
    const int tid = threadIdx.x;
    const int m0  = (tid >> 4) * 4;
    const int n0  = (tid & 15) * 4;

    const float* xb = x + (size_t)b * C_ * P_;

    const int ka0 = tid >> 5;
    const int ma4 = (tid & 31) << 2;
    const int ol0 = tid >> 2;
    const int ol1 = ol0 + 64;
    const int k4  = (tid & 3) << 2;
    const int or0 = oT + ol0;
    const int or1 = oT + ol1;
    const float* wr0 = (or0 < 256) ? (wq + or0 * 256) : (wkv + (or0 - 256) * 256);
    const float* wr1 = (or1 < 256) ? (wq + or1 * 256) : (wkv + (or1 - 256) * 256);

    float acc[8][8];
#pragma unroll
    for (int i = 0; i < 8; i++)
#pragma unroll
        for (int j = 0; j < 8; j++) acc[i][j] = 0.f;

    float4 ra0, ra1, rb0, rb1;

#define QKV_LOADG(K0)                                                          \
    {                                                                          \
        ra0 = *(const float4*)&xb[(size_t)((K0) + ka0) * P_ + pT + ma4];       \
        ra1 = *(const float4*)&xb[(size_t)((K0) + 8 + ka0) * P_ + pT + ma4];   \
        rb0 = *(const float4*)&wr0[(K0) + k4];                                 \
        rb1 = *(const float4*)&wr1[(K0) + k4];                                 \
    }
#define QKV_STORE(BUF)                                                         \
    {                                                                          \
        *(float4*)&As[BUF][ka0][ma4]     = ra0;                                \
        *(float4*)&As[BUF][8 + ka0][ma4] = ra1;                                \
        Bs[BUF][k4 + 0][ol0] = rb0.x; Bs[BUF][k4 + 1][ol0] = rb0.y;            \
        Bs[BUF][k4 + 2][ol0] = rb0.z; Bs[BUF][k4 + 3][ol0] = rb0.w;            \
        Bs[BUF][k4 + 0][ol1] = rb1.x; Bs[BUF][k4 + 1][ol1] = rb1.y;            \
        Bs[BUF][k4 + 2][ol1] = rb1.z; Bs[BUF][k4 + 3][ol1] = rb1.w;            \
    }

    QKV_LOADG(0);
    QKV_STORE(0);
    __syncthreads();

    for (int it = 0; it < 16; it++) {
        const int buf = it & 1;
        if (it < 15) QKV_LOADG((it + 1) * 16);
#pragma unroll
        for (int kk = 0; kk < 16; kk++) {
            float4 a0 = *(float4*)&As[buf][kk][m0];
            float4 a1 = *(float4*)&As[buf][kk][m0 + 64];
            float4 b0 = *(float4*)&Bs[buf][kk][n0];
            float4 b1 = *(float4*)&Bs[buf][kk][n0 + 64];
            float a[8] = {a0.x, a0.y, a0.z, a0.w, a1.x, a1.y, a1.z, a1.w};
            float bb[8] = {b0.x, b0.y, b0.z, b0.w, b1.x, b1.y, b1.z, b1.w};
#pragma unroll
            for (int i = 0; i < 8; i++)
#pragma unroll
                for (int j = 0; j < 8; j++) acc[i][j] += a[i] * bb[j];
        }
        if (it < 15) {
            QKV_STORE(buf ^ 1);
            __syncthreads();
        }
    }

#pragma unroll
    for (int i = 0; i < 8; i++) {
        int m = (i < 4) ? (m0 + i) : (m0 + 64 + (i - 4));
        float* rowp = &g_qkv[(size_t)((size_t)b * P_ + pT + m) * ROWF_];
        if (oT < 256) {
            // q range: fp32 (oT = 0 or 128)
            *(float4*)&rowp[oT + n0] =
                make_float4(acc[i][0], acc[i][1], acc[i][2], acc[i][3]);
            *(float4*)&rowp[oT + n0 + 64] =
                make_float4(acc[i][4], acc[i][5], acc[i][6], acc[i][7]);
        } else {
            // k range (oT 256/384) at float offset 256; v (512/640) at 384
            __half* hbase = (oT < 512) ? (__half*)(rowp + 256)
                                       : (__half*)(rowp + 384);
            int hb = ((oT < 512) ? (oT - 256) : (oT - 512)) + n0;
            *(__half2*)&hbase[hb]          = __floats2half2_rn(acc[i][0], acc[i][1]);
            *(__half2*)&hbase[hb + 2]      = __floats2half2_rn(acc[i][2], acc[i][3]);
            *(__half2*)&hbase[hb + 64]     = __floats2half2_rn(acc[i][4], acc[i][5]);
            *(__half2*)&hbase[hb + 64 + 2] = __floats2half2_rn(acc[i][6], acc[i][7]);
        }
    }
}

// =====================================================================
// Kernel 2: halo attention (R6 structure). 64 q/CTA, 512 threads,
// scores in regs, fp16 probs, fp16 K/V in gmem converted on load.
// =====================================================================
// smem layout (float units) — identical to R6
#define OQ_   0                                 // 64*36   = 2304
#define OK_   (OQ_ + 64 * KST_)                 // 224*36  = 8064
#define OV_   (OK_ + NKPAD_ * KST_)             // 196*36  = 7056
#define OP_   (OV_ + 196 * KST_)                // 64*200 half = 6400 fl
#define OM_   (OP_ + 6400)                      // 256
#define OL_   (OM_ + 256)                       // 256
#define OBW_  (OL_ + 256)                       // 896
#define OBH_  (OBW_ + 896)                      // 896
#define ORH_  (OBH_ + 896)                      // 864
#define ORW_  (ORH_ + 864)                      // 864
#define SMEMF_ (ORW_ + 864)                     // 27856 fl = 111424 B

__global__ __launch_bounds__(512, 2) void halo_attn_k(
    const float* __restrict__ rel_h,
    const float* __restrict__ rel_w)
{
    extern __shared__ float sm[];
    float*  sQ  = sm + OQ_;
    float*  sK  = sm + OK_;
    float*  sV  = sm + OV_;
    __half* sP  = (__half*)(sm + OP_);
    float*  sM  = sm + OM_;
    float*  sL  = sm + OL_;
    float*  sBW = sm + OBW_;
    float*  sBH = sm + OBH_;
    float*  sRH = sm + ORH_;
    float*  sRW = sm + ORW_;

    const int b    = blockIdx.y;
    const int blk  = blockIdx.x;
    const int bh   = blk >> 4;
    const int bw   = blk & 15;
    const int tid  = threadIdx.x;
    const int w    = tid >> 5;
    const int lane = tid & 31;
    const int qg   = lane >> 3;        // 0..3
    const int kg   = lane & 7;         // 0..7
    const int qt   = (w >> 2) * 16 + qg * 4;   // base q row (0..60)
    const int kt   = w & 3;                    // k tile
    const int k0   = kt * 56 + kg * 7;         // base key (0..217)
    const float scale = 0.1767766952966369f;   // 1/sqrt(32)

    const char* gb = (const char*)g_qkv + (size_t)b * P_ * (ROWF_ * 4);

    // rel tables + zero K pad rows (once)
    for (int i = tid; i < 27 * 32; i += 512) {
        sRH[i] = rel_h[i];
        sRW[i] = rel_w[i];
    }
    for (int i = tid; i < (NKPAD_ - NKEY_) * KST_; i += 512)
        sK[NKEY_ * KST_ + i] = 0.f;

    // incremental kj -> (row, col) base for this thread's 7 keys
    const int r14b = k0 / 14;
    const int c14b = k0 - r14b * 14;

    for (int hd = 0; hd < HEADS_; hd++) {
        __syncthreads();  // smem reuse guard across heads (and init)

        // ---- load Q: 64 rows x 32 (fp32) ----
        {
            int r = tid >> 3, d4 = (tid & 7) << 2;
            int p = (bh * 8 + (r >> 3)) * 128 + bw * 8 + (r & 7);
            float4 v = *(const float4*)(gb + (size_t)p * 2048 + (hd * 32 + d4) * 4);
            *(float4*)&sQ[r * KST_ + d4] = v;
        }
        // ---- load K,V: 196 rows x 32 fp16 each; convert to fp32 in smem ----
        for (int idx = tid; idx < NKEY_ * 8; idx += 512) {
            int r = idx >> 3, rem = idx & 7;
            int arr = rem >> 2, c4 = rem & 3;     // arr: 0=K 1=V; c4: 8-half chunk
            int iw = r / 14, jw = r - iw * 14;
            int hp = bh * 8 - HALO_ + iw;
            int wp = bw * 8 - HALO_ + jw;
            float4 f0 = make_float4(0.f, 0.f, 0.f, 0.f);
            float4 f1 = f0;
            if (hp >= 0 && hp < H_ && wp >= 0 && wp < W_) {
                uint4 u = *(const uint4*)(gb + (size_t)(hp * 128 + wp) * 2048
                                          + 1024 + arr * 512 + hd * 64 + c4 * 16);
                float2 t0 = __half22float2(*(__half2*)&u.x);
                float2 t1 = __half22float2(*(__half2*)&u.y);
                float2 t2 = __half22float2(*(__half2*)&u.z);
                float2 t3 = __half22float2(*(__half2*)&u.w);
                f0 = make_float4(t0.x, t0.y, t1.x, t1.y);
                f1 = make_float4(t2.x, t2.y, t3.x, t3.y);
            }
            float* dst = (arr ? sV : sK) + r * KST_ + c4 * 8;
            *(float4*)dst     = f0;
            *(float4*)(dst+4) = f1;
        }
        __syncthreads();

        // ---- rel-pos bias ----
        for (int idx = tid; idx < 64 * 14; idx += 512) {
            int qi = idx / 14, j = idx - qi * 14;
            int xq = qi >> 3, yq = qi & 7;
            const float4* qr = (const float4*)(sQ + qi * KST_);
            const float4* rw = (const float4*)(sRW + (j - yq + 13) * 32);
            const float4* rh = (const float4*)(sRH + (j - xq + 13) * 32);
            float aw = 0.f, ah = 0.f;
#pragma unroll 2
            for (int d = 0; d < 8; d++) {
                float4 q = qr[d], a = rw[d], c = rh[d];
                aw += q.x * a.x + q.y * a.y + q.z * a.z + q.w * a.w;
                ah += q.x * c.x + q.y * c.y + q.z * c.z + q.w * c.w;
            }
            sBW[idx] = aw;
            sBH[idx] = ah;
        }
        __syncthreads();

        // ---- scores in registers: 4q x 7k per thread ----
        float acc[4][7];
#pragma unroll
        for (int i = 0; i < 4; i++)
#pragma unroll
            for (int j = 0; j < 7; j++) acc[i][j] = 0.f;

        for (int ds = 0; ds < 8; ds++) {
            const int d = ds * 4;
            float4 qv[4];
#pragma unroll
            for (int i = 0; i < 4; i++) qv[i] = *(float4*)&sQ[(qt + i) * KST_ + d];
#pragma unroll
            for (int j = 0; j < 7; j++) {
                float4 kv = *(float4*)&sK[(k0 + j) * KST_ + d];
#pragma unroll
                for (int i = 0; i < 4; i++)
                    acc[i][j] += qv[i].x * kv.x + qv[i].y * kv.y
                               + qv[i].z * kv.z + qv[i].w * kv.w;
            }
        }

        // ---- epilogue (scale+bias) + per-thread max ----
        float lmax[4] = {-1e30f, -1e30f, -1e30f, -1e30f};
        {
            int rr = r14b, cc = c14b;
#pragma unroll
            for (int j = 0; j < 7; j++) {
                const int kj = k0 + j;
                const bool val = (kj < NKEY_);
#pragma unroll
                for (int i = 0; i < 4; i++) {
                    float s = acc[i][j] * scale
                            + sBW[(qt + i) * 14 + cc]
                            + sBH[(qt + i) * 14 + rr];
                    acc[i][j] = s;
                    if (val) lmax[i] = fmaxf(lmax[i], s);
                }
                cc++;
                if (cc == 14) { cc = 0; rr++; }
            }
        }
#pragma unroll
        for (int i = 0; i < 4; i++) {
#pragma unroll
            for (int o = 1; o < 8; o <<= 1)
                lmax[i] = fmaxf(lmax[i], __shfl_xor_sync(0xffffffffu, lmax[i], o));
        }
        if (kg == 0) {
#pragma unroll
            for (int i = 0; i < 4; i++) sM[(qt + i) * 4 + kt] = lmax[i];
        }
        __syncthreads();

        // ---- exp + partial sums + fp16 prob store ----
        float lsum[4] = {0.f, 0.f, 0.f, 0.f};
        {
            float m[4];
#pragma unroll
            for (int i = 0; i < 4; i++) {
                const float* mp = sM + (qt + i) * 4;
                m[i] = fmaxf(fmaxf(mp[0], mp[1]), fmaxf(mp[2], mp[3]));
            }
#pragma unroll
            for (int j = 0; j < 7; j++) {
                const int kj = k0 + j;
                if (kj < NKEY_) {
#pragma unroll
                    for (int i = 0; i < 4; i++) {
                        float e = __expf(acc[i][j] - m[i]);
                        lsum[i] += e;
                        sP[(qt + i) * 200 + kj] = __float2half_rn(e);
                    }
                }
            }
        }
#pragma unroll
        for (int i = 0; i < 4; i++) {
#pragma unroll
            for (int o = 1; o < 8; o <<= 1)
                lsum[i] += __shfl_xor_sync(0xffffffffu, lsum[i], o);
        }
        if (kg == 0) {
#pragma unroll
            for (int i = 0; i < 4; i++) sL[(qt + i) * 4 + kt] = lsum[i];
        }
        __syncthreads();

        // ---- ctx: 1q x 4d per thread; normalize at the end ----
        {
            const int q  = tid >> 3;          // 0..63
            const int d0 = (tid & 7) * 4;     // 0..28
            const float* lp = sL + q * 4;
            const float invl = 1.f / (lp[0] + lp[1] + lp[2] + lp[3]);
            float ax = 0.f, ay = 0.f, az = 0.f, aw = 0.f;
            const __half2* sp2 = (const __half2*)(sP + q * 200);
            const float* vp = sV + d0;
#pragma unroll 2
            for (int k2 = 0; k2 < NKEY_ / 2; k2++) {
                float2 ss = __half22float2(sp2[k2]);
                float4 v0 = *(float4*)&vp[(2 * k2) * KST_];
                float4 v1 = *(float4*)&vp[(2 * k2 + 1) * KST_];
                ax += ss.x * v0.x + ss.y * v1.x;
                ay += ss.x * v0.y + ss.y * v1.y;
                az += ss.x * v0.z + ss.y * v1.z;
                aw += ss.x * v0.w + ss.y * v1.w;
            }
            int p = (bh * 8 + (q >> 3)) * 128 + bw * 8 + (q & 7);
            *(float4*)&g_ctx[((size_t)b * P_ + p) * C_ + hd * 32 + d0] =
                make_float4(ax * invl, ay * invl, az * invl, aw * invl);
        }
    }
}

// =====================================================================
// Kernel 3: FC epilogue, ping-pong, reads pixel-major ctx.
// =====================================================================
#define BSTRIDE_ 132

__global__ __launch_bounds__(256) void fc_gemm_k(
    const float* __restrict__ fcw,
    const float* __restrict__ fcb,
    float* __restrict__ out)
{
    __shared__ float As[2][16][64];
    __shared__ float Bs[2][16][BSTRIDE_];

    const int pT  = blockIdx.x * 128;
    const int oT  = blockIdx.y * 64;
    const int b   = blockIdx.z;
    const int tid = threadIdx.x;
    const int m0  = (tid >> 4) * 4;
    const int n0  = (tid & 15) * 4;

    const int am = tid & 63;
    const int ak = (tid >> 6) * 4;
    const int pl = tid >> 1;
    const int cg = (tid & 1) * 4;
    const float* arow = fcw + (oT + am) * 256;
    const float* ctxb = g_ctx + ((size_t)b * P_ + pT) * C_;

    float acc[4][8];
#pragma unroll
    for (int i = 0; i < 4; i++)
#pragma unroll
        for (int j = 0; j < 8; j++) acc[i][j] = 0.f;

    float4 ra, rb0, rb1;

#define FC_LOADG(K0)                                                           \
    {                                                                          \
        ra  = *(const float4*)&arow[(K0) + ak];                                \
        rb0 = *(const float4*)&ctxb[(size_t)pl * C_ + (K0) + cg];              \
        rb1 = *(const float4*)&ctxb[(size_t)pl * C_ + (K0) + 8 + cg];          \
    }
#define FC_STORE(BUF)                                                          \
    {                                                                          \
        As[BUF][ak + 0][am] = ra.x; As[BUF][ak + 1][am] = ra.y;                \
        As[BUF][ak + 2][am] = ra.z; As[BUF][ak + 3][am] = ra.w;                \
        Bs[BUF][cg + 0][pl] = rb0.x; Bs[BUF][cg + 1][pl] = rb0.y;              \
        Bs[BUF][cg + 2][pl] = rb0.z; Bs[BUF][cg + 3][pl] = rb0.w;              \
        Bs[BUF][8 + cg + 0][pl] = rb1.x; Bs[BUF][8 + cg + 1][pl] = rb1.y;      \
        Bs[BUF][8 + cg + 2][pl] = rb1.z; Bs[BUF][8 + cg + 3][pl] = rb1.w;      \
    }

    FC_LOADG(0);
    FC_STORE(0);
    __syncthreads();

    for (int it = 0; it < 16; it++) {
        const int buf = it & 1;
        if (it < 15) FC_LOADG((it + 1) * 16);
#pragma unroll
        for (int kk = 0; kk < 16; kk++) {
            float4 av = *(float4*)&As[buf][kk][m0];
            float4 b0 = *(float4*)&Bs[buf][kk][n0];
            float4 b1 = *(float4*)&Bs[buf][kk][n0 + 64];
            float a[4] = {av.x, av.y, av.z, av.w};
            float bb[8] = {b0.x, b0.y, b0.z, b0.w, b1.x, b1.y, b1.z, b1.w};
#pragma unroll
            for (int i = 0; i < 4; i++)
#pragma unroll
                for (int j = 0; j < 8; j++) acc[i][j] += a[i] * bb[j];
        }
        if (it < 15) {
            FC_STORE(buf ^ 1);
            __syncthreads();
        }
    }

#pragma unroll
    for (int i = 0; i < 4; i++) {
        int o = oT + m0 + i;
        float bias = fcb[o];
        float* orow = out + ((size_t)b * C_ + o) * P_ + pT;
        *(float4*)&orow[n0]      = make_float4(acc[i][0] + bias, acc[i][1] + bias,
                                               acc[i][2] + bias, acc[i][3] + bias);
        *(float4*)&orow[n0 + 64] = make_float4(acc[i][4] + bias, acc[i][5] + bias,
                                               acc[i][6] + bias, acc[i][7] + bias);
    }
}

// Dummy kernel: shifts ncu's captured launch (#6 with -s 5 -c 1) onto
// halo_attn_k so the next round's profile shows attention, not qkv.
__global__ void dummy_k() {}

// =====================================================================
extern "C" void kernel_launch(void* const* d_in, const int* in_sizes, int n_in,
                              void* d_out, int out_size)
{
    const float* x   = (const float*)d_in[0];
    const float* wq  = (const float*)d_in[1];
    const float* wkv = (const float*)d_in[2];
    const float* fcw = (const float*)d_in[3];
    const float* fcb = (const float*)d_in[4];
    const float* rh  = (const float*)d_in[5];
    const float* rw  = (const float*)d_in[6];
    float* out = (float*)d_out;

    cudaFuncSetAttribute(halo_attn_k,
                         cudaFuncAttributeMaxDynamicSharedMemorySize,
                         SMEMF_ * (int)sizeof(float));

    qkv_gemm_k<<<dim3(P_ / 128, 6, B_), 256>>>(x, wq, wkv);
    halo_attn_k<<<dim3(NB_, B_), 512, SMEMF_ * sizeof(float)>>>(rh, rw);
    fc_gemm_k<<<dim3(P_ / 128, C_ / 64, B_), 256>>>(fcw, fcb, out);
    dummy_k<<<1, 32>>>();
}

// round 15
// speedup vs baseline: 1.5218x; 1.3345x over previous
#include <cuda_runtime.h>
#include <cuda_fp16.h>
#include <cstdint>

// ---------------- problem constants ----------------
#define B_     4
#define C_     256
#define H_     128
#define W_     128
#define P_     (H_ * W_)      // 16384 pixels per batch
#define HEADS_ 8
#define HALO_  3
#define NKEY_  196
#define NB_    256
#define ROWF_  384            // g_qkv row: 768 halves (q|k|v fp16) = 384 floats

// ---------------- scratch (device globals) ----------------
__device__ float g_qkv[(size_t)B_ * P_ * ROWF_];  // [b][p]: q|k|v all fp16
__device__ float g_ctx[(size_t)B_ * P_ * C_];     // [b][p][c] pixel-major fp32

// ---------------- mma / ldmatrix helpers ----------------
#define LDM_X4(A0,A1,A2,A3,ADDR)                                               \
    asm volatile("ldmatrix.sync.aligned.m8n8.x4.shared.b16 {%0,%1,%2,%3},[%4];"\
                 : "=r"(A0),"=r"(A1),"=r"(A2),"=r"(A3) : "r"(ADDR))
#define LDM_X2(B0,B1,ADDR)                                                     \
    asm volatile("ldmatrix.sync.aligned.m8n8.x2.shared.b16 {%0,%1},[%2];"      \
                 : "=r"(B0),"=r"(B1) : "r"(ADDR))
#define LDM_X2T(B0,B1,ADDR)                                                    \
    asm volatile("ldmatrix.sync.aligned.m8n8.x2.trans.shared.b16 {%0,%1},[%2];"\
                 : "=r"(B0),"=r"(B1) : "r"(ADDR))
#define MMA16816(C0,C1,C2,C3,A0,A1,A2,A3,B0,B1)                                \
    asm volatile("mma.sync.aligned.m16n8k16.row.col.f32.f16.f16.f32 "          \
                 "{%0,%1,%2,%3},{%4,%5,%6,%7},{%8,%9},{%0,%1,%2,%3};"          \
                 : "+f"(C0),"+f"(C1),"+f"(C2),"+f"(C3)                         \
                 : "r"(A0),"r"(A1),"r"(A2),"r"(A3),"r"(B0),"r"(B1))

// =====================================================================
// Kernel 1: QKV projection, ping-pong double buffered; all outputs fp16.
// =====================================================================
__global__ __launch_bounds__(256) void qkv_gemm_k(
    const float* __restrict__ x,
    const float* __restrict__ wq,
    const float* __restrict__ wkv)
{
    __shared__ float As[2][16][128];
    __shared__ float Bs[2][16][128];

    const int pT  = blockIdx.x * 128;
    const int oT  = blockIdx.y * 128;
    const int b   = blockIdx.z;
    const int tid = threadIdx.x;
    const int m0  = (tid >> 4) * 4;
    const int n0  = (tid & 15) * 4;

    const float* xb = x + (size_t)b * C_ * P_;

    const int ka0 = tid >> 5;
    const int ma4 = (tid & 31) << 2;
    const int ol0 = tid >> 2;
    const int ol1 = ol0 + 64;
    const int k4  = (tid & 3) << 2;
    const int or0 = oT + ol0;
    const int or1 = oT + ol1;
    const float* wr0 = (or0 < 256) ? (wq + or0 * 256) : (wkv + (or0 - 256) * 256);
    const float* wr1 = (or1 < 256) ? (wq + or1 * 256) : (wkv + (or1 - 256) * 256);

    float acc[8][8];
#pragma unroll
    for (int i = 0; i < 8; i++)
#pragma unroll
        for (int j = 0; j < 8; j++) acc[i][j] = 0.f;

    float4 ra0, ra1, rb0, rb1;

#define QKV_LOADG(K0)                                                          \
    {                                                                          \
        ra0 = *(const float4*)&xb[(size_t)((K0) + ka0) * P_ + pT + ma4];       \
        ra1 = *(const float4*)&xb[(size_t)((K0) + 8 + ka0) * P_ + pT + ma4];   \
        rb0 = *(const float4*)&wr0[(K0) + k4];                                 \
        rb1 = *(const float4*)&wr1[(K0) + k4];                                 \
    }
#define QKV_STORE(BUF)                                                         \
    {                                                                          \
        *(float4*)&As[BUF][ka0][ma4]     = ra0;                                \
        *(float4*)&As[BUF][8 + ka0][ma4] = ra1;                                \
        Bs[BUF][k4 + 0][ol0] = rb0.x; Bs[BUF][k4 + 1][ol0] = rb0.y;            \
        Bs[BUF][k4 + 2][ol0] = rb0.z; Bs[BUF][k4 + 3][ol0] = rb0.w;            \
        Bs[BUF][k4 + 0][ol1] = rb1.x; Bs[BUF][k4 + 1][ol1] = rb1.y;            \
        Bs[BUF][k4 + 2][ol1] = rb1.z; Bs[BUF][k4 + 3][ol1] = rb1.w;            \
    }

    QKV_LOADG(0);
    QKV_STORE(0);
    __syncthreads();

    for (int it = 0; it < 16; it++) {
        const int buf = it & 1;
        if (it < 15) QKV_LOADG((it + 1) * 16);
#pragma unroll
        for (int kk = 0; kk < 16; kk++) {
            float4 a0 = *(float4*)&As[buf][kk][m0];
            float4 a1 = *(float4*)&As[buf][kk][m0 + 64];
            float4 b0 = *(float4*)&Bs[buf][kk][n0];
            float4 b1 = *(float4*)&Bs[buf][kk][n0 + 64];
            float a[8] = {a0.x, a0.y, a0.z, a0.w, a1.x, a1.y, a1.z, a1.w};
            float bb[8] = {b0.x, b0.y, b0.z, b0.w, b1.x, b1.y, b1.z, b1.w};
#pragma unroll
            for (int i = 0; i < 8; i++)
#pragma unroll
                for (int j = 0; j < 8; j++) acc[i][j] += a[i] * bb[j];
        }
        if (it < 15) {
            QKV_STORE(buf ^ 1);
            __syncthreads();
        }
    }

#pragma unroll
    for (int i = 0; i < 8; i++) {
        int m = (i < 4) ? (m0 + i) : (m0 + 64 + (i - 4));
        __half* hrow = (__half*)&g_qkv[(size_t)((size_t)b * P_ + pT + m) * ROWF_];
        int o = oT + n0;
        *(__half2*)&hrow[o]      = __floats2half2_rn(acc[i][0], acc[i][1]);
        *(__half2*)&hrow[o + 2]  = __floats2half2_rn(acc[i][2], acc[i][3]);
        *(__half2*)&hrow[o + 64] = __floats2half2_rn(acc[i][4], acc[i][5]);
        *(__half2*)&hrow[o + 66] = __floats2half2_rn(acc[i][6], acc[i][7]);
    }
}

// =====================================================================
// Kernel 2: halo attention via tensor cores (mma.sync m16n8k16).
// 64 q/CTA, 512 threads, 2 CTAs/SM. Q/K/V/P fp16, accum fp32.
// =====================================================================
// smem byte offsets (16B aligned)
#define SB_K_   0                    // 224 x 40 halves (80B rows) = 17920
#define SB_V_   17920                // 17920
#define SB_Q_   35840                // 64 x 40 halves = 5120
#define SB_P_   40960                // 64 x 232 halves (464B rows) = 29696
#define SB_BW_  70656                // 64x14 f32 = 3584
#define SB_BH_  74240                // 3584
#define SB_M_   77824                // 64x4 f32 = 1024
#define SB_L_   78848                // 1024
#define SB_RH_  79872                // 27x32 f32 = 3456
#define SB_RW_  83328                // 3456
#define SMEMB_  86784

__global__ __launch_bounds__(512, 2) void halo_attn_k(
    const float* __restrict__ rel_h,
    const float* __restrict__ rel_w)
{
    extern __shared__ char smem[];
    const uint32_t sb = (uint32_t)__cvta_generic_to_shared(smem);

    float* sBW = (float*)(smem + SB_BW_);
    float* sBH = (float*)(smem + SB_BH_);
    float* sM  = (float*)(smem + SB_M_);
    float* sL  = (float*)(smem + SB_L_);
    float* sRH = (float*)(smem + SB_RH_);
    float* sRW = (float*)(smem + SB_RW_);

    const int b    = blockIdx.y;
    const int blk  = blockIdx.x;
    const int bh   = blk >> 4;
    const int bw   = blk & 15;
    const int tid  = threadIdx.x;
    const int w    = tid >> 5;
    const int lane = tid & 31;
    const int kt   = w & 3;            // n-chunk (score) / d-tile (ctx)
    const int qb   = (w >> 2) * 16;    // m-tile base row
    const int cb   = kt * 56;          // score col base
    const float scale = 0.1767766952966369f;   // 1/sqrt(32)

    const char* gb = (const char*)g_qkv + (size_t)b * P_ * 1536;

    // stage rel tables; zero K/V pad rows [196,224)
    for (int i = tid; i < 27 * 32; i += 512) {
        sRH[i] = rel_h[i];
        sRW[i] = rel_w[i];
    }
    if (tid < 280) {
        int arr = tid / 140, rr = tid % 140;
        int r = 196 + rr / 5, c5 = rr % 5;
        *(uint4*)(smem + (arr ? SB_V_ : SB_K_) + r * 80 + c5 * 16) =
            make_uint4(0, 0, 0, 0);
    }

    for (int hd = 0; hd < HEADS_; hd++) {
        __syncthreads();   // smem reuse guard (and init)

        // ---- load Q: 64 rows x 64B (fp16) ----
        if (tid < 256) {
            int r = tid >> 2, c = tid & 3;
            int p = (bh * 8 + (r >> 3)) * 128 + bw * 8 + (r & 7);
            uint4 u = *(const uint4*)(gb + (size_t)p * 1536 + hd * 64 + c * 16);
            *(uint4*)(smem + SB_Q_ + r * 80 + c * 16) = u;
        }
        // ---- load K,V: 196 rows x 64B each, zero-pad halo ----
        for (int idx = tid; idx < 1568; idx += 512) {
            int r = idx >> 3, rem = idx & 7;
            int arr = rem >> 2, c = rem & 3;
            int iw = r / 14, jw = r - iw * 14;
            int hp = bh * 8 - HALO_ + iw;
            int wp = bw * 8 - HALO_ + jw;
            uint4 u = make_uint4(0, 0, 0, 0);
            if (hp >= 0 && hp < H_ && wp >= 0 && wp < W_)
                u = *(const uint4*)(gb + (size_t)(hp * 128 + wp) * 1536
                                    + 512 + arr * 512 + hd * 64 + c * 16);
            *(uint4*)(smem + (arr ? SB_V_ : SB_K_) + r * 80 + c * 16) = u;
        }
        __syncthreads();

        // ---- rel-pos bias tables: sBW[q][j], sBH[q][j] ----
        for (int idx = tid; idx < 64 * 14; idx += 512) {
            int qi = idx / 14, j = idx - qi * 14;
            int xq = qi >> 3, yq = qi & 7;
            const __half2* q2p = (const __half2*)(smem + SB_Q_ + qi * 80);
            const float* rwp = sRW + (j - yq + 13) * 32;
            const float* rhp = sRH + (j - xq + 13) * 32;
            float aw = 0.f, ah = 0.f;
#pragma unroll
            for (int d2 = 0; d2 < 16; d2++) {
                float2 q = __half22float2(q2p[d2]);
                aw += q.x * rwp[2 * d2] + q.y * rwp[2 * d2 + 1];
                ah += q.x * rhp[2 * d2] + q.y * rhp[2 * d2 + 1];
            }
            sBW[idx] = aw;
            sBH[idx] = ah;
        }
        __syncthreads();

        // ---- score mma: warp covers rows [qb,qb+16) x cols [cb,cb+56) ----
        float c[7][4];
#pragma unroll
        for (int nt = 0; nt < 7; nt++)
#pragma unroll
            for (int i = 0; i < 4; i++) c[nt][i] = 0.f;
        {
            const uint32_t aBase = sb + SB_Q_
                + (qb + (lane & 7) + ((lane >> 3) & 1) * 8) * 80
                + ((lane >> 4) & 1) * 16;
            const uint32_t bRow = cb + (lane & 7);
            const uint32_t bSel = ((lane >> 3) & 1) * 16;
#pragma unroll
            for (int kk = 0; kk < 2; kk++) {
                uint32_t a0, a1, a2, a3;
                LDM_X4(a0, a1, a2, a3, aBase + kk * 32);
#pragma unroll
                for (int nt = 0; nt < 7; nt++) {
                    uint32_t b0, b1;
                    LDM_X2(b0, b1, sb + SB_K_ + (bRow + nt * 8) * 80 + bSel + kk * 32);
                    MMA16816(c[nt][0], c[nt][1], c[nt][2], c[nt][3],
                             a0, a1, a2, a3, b0, b1);
                }
            }
        }

        // ---- epilogue: scale + bias + row max ----
        const int r1 = qb + (lane >> 2);
        const int r2 = r1 + 8;
        float m1 = -1e30f, m2 = -1e30f;
#pragma unroll
        for (int nt = 0; nt < 7; nt++) {
            int col = cb + nt * 8 + 2 * (lane & 3);
            if (col < NKEY_) {
                int dv0 = col / 14,        cm0 = col - dv0 * 14;
                int dv1 = (col + 1) / 14,  cm1 = (col + 1) - dv1 * 14;
                float s0 = c[nt][0] * scale + sBW[r1 * 14 + cm0] + sBH[r1 * 14 + dv0];
                float s1 = c[nt][1] * scale + sBW[r1 * 14 + cm1] + sBH[r1 * 14 + dv1];
                float s2 = c[nt][2] * scale + sBW[r2 * 14 + cm0] + sBH[r2 * 14 + dv0];
                float s3 = c[nt][3] * scale + sBW[r2 * 14 + cm1] + sBH[r2 * 14 + dv1];
                c[nt][0] = s0; c[nt][1] = s1; c[nt][2] = s2; c[nt][3] = s3;
                m1 = fmaxf(m1, fmaxf(s0, s1));
                m2 = fmaxf(m2, fmaxf(s2, s3));
            } else {
                c[nt][0] = c[nt][1] = c[nt][2] = c[nt][3] = -1e30f;
            }
        }
        m1 = fmaxf(m1, __shfl_xor_sync(0xffffffffu, m1, 1));
        m1 = fmaxf(m1, __shfl_xor_sync(0xffffffffu, m1, 2));
        m2 = fmaxf(m2, __shfl_xor_sync(0xffffffffu, m2, 1));
        m2 = fmaxf(m2, __shfl_xor_sync(0xffffffffu, m2, 2));
        if ((lane & 3) == 0) {
            sM[r1 * 4 + kt] = m1;
            sM[r2 * 4 + kt] = m2;
        }
        __syncthreads();

        // ---- exp + fp16 prob store + partial sums ----
        float M1, M2;
        {
            const float* mp1 = sM + r1 * 4;
            const float* mp2 = sM + r2 * 4;
            M1 = fmaxf(fmaxf(mp1[0], mp1[1]), fmaxf(mp1[2], mp1[3]));
            M2 = fmaxf(fmaxf(mp2[0], mp2[1]), fmaxf(mp2[2], mp2[3]));
        }
        float s1 = 0.f, s2 = 0.f;
#pragma unroll
        for (int nt = 0; nt < 7; nt++) {
            int col = cb + nt * 8 + 2 * (lane & 3);
            __half2 h1, h2;
            if (col < NKEY_) {
                float e0 = __expf(c[nt][0] - M1);
                float e1 = __expf(c[nt][1] - M1);
                float e2 = __expf(c[nt][2] - M2);
                float e3 = __expf(c[nt][3] - M2);
                s1 += e0 + e1;
                s2 += e2 + e3;
                h1 = __floats2half2_rn(e0, e1);
                h2 = __floats2half2_rn(e2, e3);
            } else {
                h1 = __floats2half2_rn(0.f, 0.f);
                h2 = h1;
            }
            *(__half2*)(smem + SB_P_ + r1 * 464 + col * 2) = h1;
            *(__half2*)(smem + SB_P_ + r2 * 464 + col * 2) = h2;
        }
        s1 += __shfl_xor_sync(0xffffffffu, s1, 1);
        s1 += __shfl_xor_sync(0xffffffffu, s1, 2);
        s2 += __shfl_xor_sync(0xffffffffu, s2, 1);
        s2 += __shfl_xor_sync(0xffffffffu, s2, 2);
        if ((lane & 3) == 0) {
            sL[r1 * 4 + kt] = s1;
            sL[r2 * 4 + kt] = s2;
        }
        __syncthreads();

        // ---- ctx mma: O[qb..qb+16) x d-tile kt*8 over 224 keys ----
        float o0 = 0.f, o1 = 0.f, o2 = 0.f, o3 = 0.f;
        {
            const uint32_t aP = sb + SB_P_
                + (qb + (lane & 7) + ((lane >> 3) & 1) * 8) * 464
                + ((lane >> 4) & 1) * 16;
            const uint32_t vCol = (uint32_t)kt * 16;   // d0*2 bytes
#pragma unroll
            for (int kk = 0; kk < 14; kk++) {
                uint32_t a0, a1, a2, a3, b0, b1;
                LDM_X4(a0, a1, a2, a3, aP + kk * 32);
                uint32_t vRow = kk * 16 + (lane & 7) + ((lane >> 3) & 1) * 8;
                LDM_X2T(b0, b1, sb + SB_V_ + vRow * 80 + vCol);
                MMA16816(o0, o1, o2, o3, a0, a1, a2, a3, b0, b1);
            }
        }
        // ---- normalize + store ----
        {
            const float* lp1 = sL + r1 * 4;
            const float* lp2 = sL + r2 * 4;
            float inv1 = 1.f / (lp1[0] + lp1[1] + lp1[2] + lp1[3]);
            float inv2 = 1.f / (lp2[0] + lp2[1] + lp2[2] + lp2[3]);
            int dc = kt * 8 + 2 * (lane & 3);
            int p1 = (bh * 8 + (r1 >> 3)) * 128 + bw * 8 + (r1 & 7);
            int p2 = (bh * 8 + (r2 >> 3)) * 128 + bw * 8 + (r2 & 7);
            *(float2*)&g_ctx[((size_t)b * P_ + p1) * C_ + hd * 32 + dc] =
                make_float2(o0 * inv1, o1 * inv1);
            *(float2*)&g_ctx[((size_t)b * P_ + p2) * C_ + hd * 32 + dc] =
                make_float2(o2 * inv2, o3 * inv2);
        }
    }
}

// =====================================================================
// Kernel 3: FC epilogue, ping-pong, reads pixel-major ctx.
// =====================================================================
#define BSTRIDE_ 132

__global__ __launch_bounds__(256) void fc_gemm_k(
    const float* __restrict__ fcw,
    const float* __restrict__ fcb,
    float* __restrict__ out)
{
    __shared__ float As[2][16][64];
    __shared__ float Bs[2][16][BSTRIDE_];

    const int pT  = blockIdx.x * 128;
    const int oT  = blockIdx.y * 64;
    const int b   = blockIdx.z;
    const int tid = threadIdx.x;
    const int m0  = (tid >> 4) * 4;
    const int n0  = (tid & 15) * 4;

    const int am = tid & 63;
    const int ak = (tid >> 6) * 4;
    const int pl = tid >> 1;
    const int cg = (tid & 1) * 4;
    const float* arow = fcw + (oT + am) * 256;
    const float* ctxb = g_ctx + ((size_t)b * P_ + pT) * C_;

    float acc[4][8];
#pragma unroll
    for (int i = 0; i < 4; i++)
#pragma unroll
        for (int j = 0; j < 8; j++) acc[i][j] = 0.f;

    float4 ra, rb0, rb1;

#define FC_LOADG(K0)                                                           \
    {                                                                          \
        ra  = *(const float4*)&arow[(K0) + ak];                                \
        rb0 = *(const float4*)&ctxb[(size_t)pl * C_ + (K0) + cg];              \
        rb1 = *(const float4*)&ctxb[(size_t)pl * C_ + (K0) + 8 + cg];          \
    }
#define FC_STORE(BUF)                                                          \
    {                                                                          \
        As[BUF][ak + 0][am] = ra.x; As[BUF][ak + 1][am] = ra.y;                \
        As[BUF][ak + 2][am] = ra.z; As[BUF][ak + 3][am] = ra.w;                \
        Bs[BUF][cg + 0][pl] = rb0.x; Bs[BUF][cg + 1][pl] = rb0.y;              \
        Bs[BUF][cg + 2][pl] = rb0.z; Bs[BUF][cg + 3][pl] = rb0.w;              \
        Bs[BUF][8 + cg + 0][pl] = rb1.x; Bs[BUF][8 + cg + 1][pl] = rb1.y;      \
        Bs[BUF][8 + cg + 2][pl] = rb1.z; Bs[BUF][8 + cg + 3][pl] = rb1.w;      \
    }

    FC_LOADG(0);
    FC_STORE(0);
    __syncthreads();

    for (int it = 0; it < 16; it++) {
        const int buf = it & 1;
        if (it < 15) FC_LOADG((it + 1) * 16);
#pragma unroll
        for (int kk = 0; kk < 16; kk++) {
            float4 av = *(float4*)&As[buf][kk][m0];
            float4 b0 = *(float4*)&Bs[buf][kk][n0];
            float4 b1 = *(float4*)&Bs[buf][kk][n0 + 64];
            float a[4] = {av.x, av.y, av.z, av.w};
            float bb[8] = {b0.x, b0.y, b0.z, b0.w, b1.x, b1.y, b1.z, b1.w};
#pragma unroll
            for (int i = 0; i < 4; i++)
#pragma unroll
                for (int j = 0; j < 8; j++) acc[i][j] += a[i] * bb[j];
        }
        if (it < 15) {
            FC_STORE(buf ^ 1);
            __syncthreads();
        }
    }

#pragma unroll
    for (int i = 0; i < 4; i++) {
        int o = oT + m0 + i;
        float bias = fcb[o];
        float* orow = out + ((size_t)b * C_ + o) * P_ + pT;
        *(float4*)&orow[n0]      = make_float4(acc[i][0] + bias, acc[i][1] + bias,
                                               acc[i][2] + bias, acc[i][3] + bias);
        *(float4*)&orow[n0 + 64] = make_float4(acc[i][4] + bias, acc[i][5] + bias,
                                               acc[i][6] + bias, acc[i][7] + bias);
    }
}

// Pad kernels: with two pads before qkv, attention lands at overall
// launch #4 = the ncu capture slot observed in R1-R11.
__global__ void pad_k() {}

// =====================================================================
extern "C" void kernel_launch(void* const* d_in, const int* in_sizes, int n_in,
                              void* d_out, int out_size)
{
    const float* x   = (const float*)d_in[0];
    const float* wq  = (const float*)d_in[1];
    const float* wkv = (const float*)d_in[2];
    const float* fcw = (const float*)d_in[3];
    const float* fcb = (const float*)d_in[4];
    const float* rh  = (const float*)d_in[5];
    const float* rw  = (const float*)d_in[6];
    float* out = (float*)d_out;

    cudaFuncSetAttribute(halo_attn_k,
                         cudaFuncAttributeMaxDynamicSharedMemorySize, SMEMB_);

    pad_k<<<1, 32>>>();
    pad_k<<<1, 32>>>();
    qkv_gemm_k<<<dim3(P_ / 128, 6, B_), 256>>>(x, wq, wkv);
    halo_attn_k<<<dim3(NB_, B_), 512, SMEMB_>>>(rh, rw);
    fc_gemm_k<<<dim3(P_ / 128, C_ / 64, B_), 256>>>(fcw, fcb, out);
}

// round 16
// speedup vs baseline: 2.0510x; 1.3478x over previous
#include <cuda_runtime.h>
#include <cuda_fp16.h>
#include <cstdint>

// ---------------- problem constants ----------------
#define B_     4
#define C_     256
#define H_     128
#define W_     128
#define P_     (H_ * W_)      // 16384 pixels per batch
#define HEADS_ 8
#define HALO_  3
#define NKEY_  196
#define NB_    256
#define ROWF_  384            // g_qkv row: 768 halves (q|k|v fp16) = 384 floats

// ---------------- scratch (device globals) ----------------
__device__ float g_qkv[(size_t)B_ * P_ * ROWF_];  // [b][p]: q|k|v all fp16
__device__ float g_ctx[(size_t)B_ * P_ * C_];     // [b][p][c] pixel-major fp32

// ---------------- mma / ldmatrix helpers ----------------
#define LDM_X4(A0,A1,A2,A3,ADDR)                                               \
    asm volatile("ldmatrix.sync.aligned.m8n8.x4.shared.b16 {%0,%1,%2,%3},[%4];"\
                 : "=r"(A0),"=r"(A1),"=r"(A2),"=r"(A3) : "r"(ADDR))
#define LDM_X2(B0,B1,ADDR)                                                     \
    asm volatile("ldmatrix.sync.aligned.m8n8.x2.shared.b16 {%0,%1},[%2];"      \
                 : "=r"(B0),"=r"(B1) : "r"(ADDR))
#define LDM_X2T(B0,B1,ADDR)                                                    \
    asm volatile("ldmatrix.sync.aligned.m8n8.x2.trans.shared.b16 {%0,%1},[%2];"\
                 : "=r"(B0),"=r"(B1) : "r"(ADDR))
#define MMA16816(C0,C1,C2,C3,A0,A1,A2,A3,B0,B1)                                \
    asm volatile("mma.sync.aligned.m16n8k16.row.col.f32.f16.f16.f32 "          \
                 "{%0,%1,%2,%3},{%4,%5,%6,%7},{%8,%9},{%0,%1,%2,%3};"          \
                 : "+f"(C0),"+f"(C1),"+f"(C2),"+f"(C3)                         \
                 : "r"(A0),"r"(A1),"r"(A2),"r"(A3),"r"(B0),"r"(B1))

// =====================================================================
// Kernel 1: QKV projection, ping-pong double buffered; all outputs fp16.
// =====================================================================
__global__ __launch_bounds__(256) void qkv_gemm_k(
    const float* __restrict__ x,
    const float* __restrict__ wq,
    const float* __restrict__ wkv)
{
    __shared__ float As[2][16][128];
    __shared__ float Bs[2][16][128];

    const int pT  = blockIdx.x * 128;
    const int oT  = blockIdx.y * 128;
    const int b   = blockIdx.z;
    const int tid = threadIdx.x;
    const int m0  = (tid >> 4) * 4;
    const int n0  = (tid & 15) * 4;

    const float* xb = x + (size_t)b * C_ * P_;

    const int ka0 = tid >> 5;
    const int ma4 = (tid & 31) << 2;
    const int ol0 = tid >> 2;
    const int ol1 = ol0 + 64;
    const int k4  = (tid & 3) << 2;
    const int or0 = oT + ol0;
    const int or1 = oT + ol1;
    const float* wr0 = (or0 < 256) ? (wq + or0 * 256) : (wkv + (or0 - 256) * 256);
    const float* wr1 = (or1 < 256) ? (wq + or1 * 256) : (wkv + (or1 - 256) * 256);

    float acc[8][8];
#pragma unroll
    for (int i = 0; i < 8; i++)
#pragma unroll
        for (int j = 0; j < 8; j++) acc[i][j] = 0.f;

    float4 ra0, ra1, rb0, rb1;

#define QKV_LOADG(K0)                                                          \
    {                                                                          \
        ra0 = *(const float4*)&xb[(size_t)((K0) + ka0) * P_ + pT + ma4];       \
        ra1 = *(const float4*)&xb[(size_t)((K0) + 8 + ka0) * P_ + pT + ma4];   \
        rb0 = *(const float4*)&wr0[(K0) + k4];                                 \
        rb1 = *(const float4*)&wr1[(K0) + k4];                                 \
    }
#define QKV_STORE(BUF)                                                         \
    {                                                                          \
        *(float4*)&As[BUF][ka0][ma4]     = ra0;                                \
        *(float4*)&As[BUF][8 + ka0][ma4] = ra1;                                \
        Bs[BUF][k4 + 0][ol0] = rb0.x; Bs[BUF][k4 + 1][ol0] = rb0.y;            \
        Bs[BUF][k4 + 2][ol0] = rb0.z; Bs[BUF][k4 + 3][ol0] = rb0.w;            \
        Bs[BUF][k4 + 0][ol1] = rb1.x; Bs[BUF][k4 + 1][ol1] = rb1.y;            \
        Bs[BUF][k4 + 2][ol1] = rb1.z; Bs[BUF][k4 + 3][ol1] = rb1.w;            \
    }

    QKV_LOADG(0);
    QKV_STORE(0);
    __syncthreads();

    for (int it = 0; it < 16; it++) {
        const int buf = it & 1;
        if (it < 15) QKV_LOADG((it + 1) * 16);
#pragma unroll
        for (int kk = 0; kk < 16; kk++) {
            float4 a0 = *(float4*)&As[buf][kk][m0];
            float4 a1 = *(float4*)&As[buf][kk][m0 + 64];
            float4 b0 = *(float4*)&Bs[buf][kk][n0];
            float4 b1 = *(float4*)&Bs[buf][kk][n0 + 64];
            float a[8] = {a0.x, a0.y, a0.z, a0.w, a1.x, a1.y, a1.z, a1.w};
            float bb[8] = {b0.x, b0.y, b0.z, b0.w, b1.x, b1.y, b1.z, b1.w};
#pragma unroll
            for (int i = 0; i < 8; i++)
#pragma unroll
                for (int j = 0; j < 8; j++) acc[i][j] += a[i] * bb[j];
        }
        if (it < 15) {
            QKV_STORE(buf ^ 1);
            __syncthreads();
        }
    }

#pragma unroll
    for (int i = 0; i < 8; i++) {
        int m = (i < 4) ? (m0 + i) : (m0 + 64 + (i - 4));
        __half* hrow = (__half*)&g_qkv[(size_t)((size_t)b * P_ + pT + m) * ROWF_];
        int o = oT + n0;
        *(__half2*)&hrow[o]      = __floats2half2_rn(acc[i][0], acc[i][1]);
        *(__half2*)&hrow[o + 2]  = __floats2half2_rn(acc[i][2], acc[i][3]);
        *(__half2*)&hrow[o + 64] = __floats2half2_rn(acc[i][4], acc[i][5]);
        *(__half2*)&hrow[o + 66] = __floats2half2_rn(acc[i][6], acc[i][7]);
    }
}

// =====================================================================
// Kernel 2: halo attention via tensor cores (mma.sync m16n8k16).
// 64 q/CTA, 512 threads, 2 CTAs/SM. Q/K/V/P fp16, accum fp32.
// Rel tables stored TRANSPOSED [d][t] (stride 28) -> conflict-free bias.
// =====================================================================
// smem byte offsets (16B aligned)
#define SB_K_   0                    // 224 x 40 halves (80B rows) = 17920
#define SB_V_   17920                // 17920
#define SB_Q_   35840                // 64 x 40 halves = 5120
#define SB_P_   40960                // 64 x 232 halves (464B rows) = 29696
#define SB_BW_  70656                // 64x14 f32 = 3584
#define SB_BH_  74240                // 3584
#define SB_M_   77824                // 64x4 f32 = 1024
#define SB_L_   78848                // 1024
#define SB_RH_  79872                // 32x28 f32 transposed = 3584
#define SB_RW_  83456                // 3584
#define SMEMB_  87040

__global__ __launch_bounds__(512, 2) void halo_attn_k(
    const float* __restrict__ rel_h,
    const float* __restrict__ rel_w)
{
    extern __shared__ char smem[];
    const uint32_t sb = (uint32_t)__cvta_generic_to_shared(smem);

    float* sBW = (float*)(smem + SB_BW_);
    float* sBH = (float*)(smem + SB_BH_);
    float* sM  = (float*)(smem + SB_M_);
    float* sL  = (float*)(smem + SB_L_);
    float* sRH = (float*)(smem + SB_RH_);   // [d][t] stride 28
    float* sRW = (float*)(smem + SB_RW_);   // [d][t] stride 28

    const int b    = blockIdx.y;
    const int blk  = blockIdx.x;
    const int bh   = blk >> 4;
    const int bw   = blk & 15;
    const int tid  = threadIdx.x;
    const int w    = tid >> 5;
    const int lane = tid & 31;
    const int kt   = w & 3;            // n-chunk (score) / d-tile (ctx)
    const int qb   = (w >> 2) * 16;    // m-tile base row
    const int cb   = kt * 56;          // score col base
    const float scale = 0.1767766952966369f;   // 1/sqrt(32)

    const char* gb = (const char*)g_qkv + (size_t)b * P_ * 1536;

    // stage rel tables TRANSPOSED; zero K/V pad rows [196,224)
    for (int i = tid; i < 27 * 32; i += 512) {
        int t = i >> 5, d = i & 31;          // input layout [t][d]
        sRH[d * 28 + t] = rel_h[i];
        sRW[d * 28 + t] = rel_w[i];
    }
    if (tid < 280) {
        int arr = tid / 140, rr = tid % 140;
        int r = 196 + rr / 5, c5 = rr % 5;
        *(uint4*)(smem + (arr ? SB_V_ : SB_K_) + r * 80 + c5 * 16) =
            make_uint4(0, 0, 0, 0);
    }

    for (int hd = 0; hd < HEADS_; hd++) {
        __syncthreads();   // smem reuse guard (and init)

        // ---- load Q: 64 rows x 64B (fp16) ----
        if (tid < 256) {
            int r = tid >> 2, c = tid & 3;
            int p = (bh * 8 + (r >> 3)) * 128 + bw * 8 + (r & 7);
            uint4 u = *(const uint4*)(gb + (size_t)p * 1536 + hd * 64 + c * 16);
            *(uint4*)(smem + SB_Q_ + r * 80 + c * 16) = u;
        }
        // ---- load K,V: 196 rows x 64B each, zero-pad halo ----
        for (int idx = tid; idx < 1568; idx += 512) {
            int r = idx >> 3, rem = idx & 7;
            int arr = rem >> 2, c = rem & 3;
            int iw = r / 14, jw = r - iw * 14;
            int hp = bh * 8 - HALO_ + iw;
            int wp = bw * 8 - HALO_ + jw;
            uint4 u = make_uint4(0, 0, 0, 0);
            if (hp >= 0 && hp < H_ && wp >= 0 && wp < W_)
                u = *(const uint4*)(gb + (size_t)(hp * 128 + wp) * 1536
                                    + 512 + arr * 512 + hd * 64 + c * 16);
            *(uint4*)(smem + (arr ? SB_V_ : SB_K_) + r * 80 + c * 16) = u;
        }
        __syncthreads();

        // ---- rel-pos bias tables (conflict-free transposed reads) ----
        for (int idx = tid; idx < 64 * 14; idx += 512) {
            int qi = idx / 14, j = idx - qi * 14;
            int xq = qi >> 3, yq = qi & 7;
            int jw = j - yq + 13;
            int jh = j - xq + 13;
            const __half2* q2p = (const __half2*)(smem + SB_Q_ + qi * 80);
            float aw = 0.f, ah = 0.f;
#pragma unroll
            for (int d2 = 0; d2 < 16; d2++) {
                float2 q = __half22float2(q2p[d2]);
                aw += q.x * sRW[(2 * d2) * 28 + jw] + q.y * sRW[(2 * d2 + 1) * 28 + jw];
                ah += q.x * sRH[(2 * d2) * 28 + jh] + q.y * sRH[(2 * d2 + 1) * 28 + jh];
            }
            sBW[idx] = aw;
            sBH[idx] = ah;
        }
        __syncthreads();

        // ---- score mma: warp covers rows [qb,qb+16) x cols [cb,cb+56) ----
        float c[7][4];
#pragma unroll
        for (int nt = 0; nt < 7; nt++)
#pragma unroll
            for (int i = 0; i < 4; i++) c[nt][i] = 0.f;
        {
            const uint32_t aBase = sb + SB_Q_
                + (qb + (lane & 7) + ((lane >> 3) & 1) * 8) * 80
                + ((lane >> 4) & 1) * 16;
            const uint32_t bRow = cb + (lane & 7);
            const uint32_t bSel = ((lane >> 3) & 1) * 16;
#pragma unroll
            for (int kk = 0; kk < 2; kk++) {
                uint32_t a0, a1, a2, a3;
                LDM_X4(a0, a1, a2, a3, aBase + kk * 32);
#pragma unroll
                for (int nt = 0; nt < 7; nt++) {
                    uint32_t b0, b1;
                    LDM_X2(b0, b1, sb + SB_K_ + (bRow + nt * 8) * 80 + bSel + kk * 32);
                    MMA16816(c[nt][0], c[nt][1], c[nt][2], c[nt][3],
                             a0, a1, a2, a3, b0, b1);
                }
            }
        }

        // ---- epilogue: scale + bias + row max ----
        const int r1 = qb + (lane >> 2);
        const int r2 = r1 + 8;
        float m1 = -1e30f, m2 = -1e30f;
#pragma unroll
        for (int nt = 0; nt < 7; nt++) {
            int col = cb + nt * 8 + 2 * (lane & 3);
            if (col < NKEY_) {
                int dv0 = col / 14,        cm0 = col - dv0 * 14;
                int dv1 = (col + 1) / 14,  cm1 = (col + 1) - dv1 * 14;
                float s0 = c[nt][0] * scale + sBW[r1 * 14 + cm0] + sBH[r1 * 14 + dv0];
                float s1 = c[nt][1] * scale + sBW[r1 * 14 + cm1] + sBH[r1 * 14 + dv1];
                float s2 = c[nt][2] * scale + sBW[r2 * 14 + cm0] + sBH[r2 * 14 + dv0];
                float s3 = c[nt][3] * scale + sBW[r2 * 14 + cm1] + sBH[r2 * 14 + dv1];
                c[nt][0] = s0; c[nt][1] = s1; c[nt][2] = s2; c[nt][3] = s3;
                m1 = fmaxf(m1, fmaxf(s0, s1));
                m2 = fmaxf(m2, fmaxf(s2, s3));
            } else {
                c[nt][0] = c[nt][1] = c[nt][2] = c[nt][3] = -1e30f;
            }
        }
        m1 = fmaxf(m1, __shfl_xor_sync(0xffffffffu, m1, 1));
        m1 = fmaxf(m1, __shfl_xor_sync(0xffffffffu, m1, 2));
        m2 = fmaxf(m2, __shfl_xor_sync(0xffffffffu, m2, 1));
        m2 = fmaxf(m2, __shfl_xor_sync(0xffffffffu, m2, 2));
        if ((lane & 3) == 0) {
            sM[r1 * 4 + kt] = m1;
            sM[r2 * 4 + kt] = m2;
        }
        __syncthreads();

        // ---- exp + fp16 prob store + partial sums ----
        float M1, M2;
        {
            const float* mp1 = sM + r1 * 4;
            const float* mp2 = sM + r2 * 4;
            M1 = fmaxf(fmaxf(mp1[0], mp1[1]), fmaxf(mp1[2], mp1[3]));
            M2 = fmaxf(fmaxf(mp2[0], mp2[1]), fmaxf(mp2[2], mp2[3]));
        }
        float s1 = 0.f, s2 = 0.f;
#pragma unroll
        for (int nt = 0; nt < 7; nt++) {
            int col = cb + nt * 8 + 2 * (lane & 3);
            __half2 h1, h2;
            if (col < NKEY_) {
                float e0 = __expf(c[nt][0] - M1);
                float e1 = __expf(c[nt][1] - M1);
                float e2 = __expf(c[nt][2] - M2);
                float e3 = __expf(c[nt][3] - M2);
                s1 += e0 + e1;
                s2 += e2 + e3;
                h1 = __floats2half2_rn(e0, e1);
                h2 = __floats2half2_rn(e2, e3);
            } else {
                h1 = __floats2half2_rn(0.f, 0.f);
                h2 = h1;
            }
            *(__half2*)(smem + SB_P_ + r1 * 464 + col * 2) = h1;
            *(__half2*)(smem + SB_P_ + r2 * 464 + col * 2) = h2;
        }
        s1 += __shfl_xor_sync(0xffffffffu, s1, 1);
        s1 += __shfl_xor_sync(0xffffffffu, s1, 2);
        s2 += __shfl_xor_sync(0xffffffffu, s2, 1);
        s2 += __shfl_xor_sync(0xffffffffu, s2, 2);
        if ((lane & 3) == 0) {
            sL[r1 * 4 + kt] = s1;
            sL[r2 * 4 + kt] = s2;
        }
        __syncthreads();

        // ---- ctx mma: O[qb..qb+16) x d-tile kt*8 over 224 keys ----
        float o0 = 0.f, o1 = 0.f, o2 = 0.f, o3 = 0.f;
        {
            const uint32_t aP = sb + SB_P_
                + (qb + (lane & 7) + ((lane >> 3) & 1) * 8) * 464
                + ((lane >> 4) & 1) * 16;
            const uint32_t vCol = (uint32_t)kt * 16;   // d0*2 bytes
#pragma unroll
            for (int kk = 0; kk < 14; kk++) {
                uint32_t a0, a1, a2, a3, b0, b1;
                LDM_X4(a0, a1, a2, a3, aP + kk * 32);
                uint32_t vRow = kk * 16 + (lane & 7) + ((lane >> 3) & 1) * 8;
                LDM_X2T(b0, b1, sb + SB_V_ + vRow * 80 + vCol);
                MMA16816(o0, o1, o2, o3, a0, a1, a2, a3, b0, b1);
            }
        }
        // ---- normalize + store ----
        {
            const float* lp1 = sL + r1 * 4;
            const float* lp2 = sL + r2 * 4;
            float inv1 = 1.f / (lp1[0] + lp1[1] + lp1[2] + lp1[3]);
            float inv2 = 1.f / (lp2[0] + lp2[1] + lp2[2] + lp2[3]);
            int dc = kt * 8 + 2 * (lane & 3);
            int p1 = (bh * 8 + (r1 >> 3)) * 128 + bw * 8 + (r1 & 7);
            int p2 = (bh * 8 + (r2 >> 3)) * 128 + bw * 8 + (r2 & 7);
            *(float2*)&g_ctx[((size_t)b * P_ + p1) * C_ + hd * 32 + dc] =
                make_float2(o0 * inv1, o1 * inv1);
            *(float2*)&g_ctx[((size_t)b * P_ + p2) * C_ + hd * 32 + dc] =
                make_float2(o2 * inv2, o3 * inv2);
        }
    }
}

// =====================================================================
// Kernel 3: FC epilogue, ping-pong, reads pixel-major ctx.
// =====================================================================
#define BSTRIDE_ 132

__global__ __launch_bounds__(256) void fc_gemm_k(
    const float* __restrict__ fcw,
    const float* __restrict__ fcb,
    float* __restrict__ out)
{
    __shared__ float As[2][16][64];
    __shared__ float Bs[2][16][BSTRIDE_];

    const int pT  = blockIdx.x * 128;
    const int oT  = blockIdx.y * 64;
    const int b   = blockIdx.z;
    const int tid = threadIdx.x;
    const int m0  = (tid >> 4) * 4;
    const int n0  = (tid & 15) * 4;

    const int am = tid & 63;
    const int ak = (tid >> 6) * 4;
    const int pl = tid >> 1;
    const int cg = (tid & 1) * 4;
    const float* arow = fcw + (oT + am) * 256;
    const float* ctxb = g_ctx + ((size_t)b * P_ + pT) * C_;

    float acc[4][8];
#pragma unroll
    for (int i = 0; i < 4; i++)
#pragma unroll
        for (int j = 0; j < 8; j++) acc[i][j] = 0.f;

    float4 ra, rb0, rb1;

#define FC_LOADG(K0)                                                           \
    {                                                                          \
        ra  = *(const float4*)&arow[(K0) + ak];                                \
        rb0 = *(const float4*)&ctxb[(size_t)pl * C_ + (K0) + cg];              \
        rb1 = *(const float4*)&ctxb[(size_t)pl * C_ + (K0) + 8 + cg];          \
    }
#define FC_STORE(BUF)                                                          \
    {                                                                          \
        As[BUF][ak + 0][am] = ra.x; As[BUF][ak + 1][am] = ra.y;                \
        As[BUF][ak + 2][am] = ra.z; As[BUF][ak + 3][am] = ra.w;                \
        Bs[BUF][cg + 0][pl] = rb0.x; Bs[BUF][cg + 1][pl] = rb0.y;              \
        Bs[BUF][cg + 2][pl] = rb0.z; Bs[BUF][cg + 3][pl] = rb0.w;              \
        Bs[BUF][8 + cg + 0][pl] = rb1.x; Bs[BUF][8 + cg + 1][pl] = rb1.y;      \
        Bs[BUF][8 + cg + 2][pl] = rb1.z; Bs[BUF][8 + cg + 3][pl] = rb1.w;      \
    }

    FC_LOADG(0);
    FC_STORE(0);
    __syncthreads();

    for (int it = 0; it < 16; it++) {
        const int buf = it & 1;
        if (it < 15) FC_LOADG((it + 1) * 16);
#pragma unroll
        for (int kk = 0; kk < 16; kk++) {
            float4 av = *(float4*)&As[buf][kk][m0];
            float4 b0 = *(float4*)&Bs[buf][kk][n0];
            float4 b1 = *(float4*)&Bs[buf][kk][n0 + 64];
            float a[4] = {av.x, av.y, av.z, av.w};
            float bb[8] = {b0.x, b0.y, b0.z, b0.w, b1.x, b1.y, b1.z, b1.w};
#pragma unroll
            for (int i = 0; i < 4; i++)
#pragma unroll
                for (int j = 0; j < 8; j++) acc[i][j] += a[i] * bb[j];
        }
        if (it < 15) {
            FC_STORE(buf ^ 1);
            __syncthreads();
        }
    }

#pragma unroll
    for (int i = 0; i < 4; i++) {
        int o = oT + m0 + i;
        float bias = fcb[o];
        float* orow = out + ((size_t)b * C_ + o) * P_ + pT;
        *(float4*)&orow[n0]      = make_float4(acc[i][0] + bias, acc[i][1] + bias,
                                               acc[i][2] + bias, acc[i][3] + bias);
        *(float4*)&orow[n0 + 64] = make_float4(acc[i][4] + bias, acc[i][5] + bias,
                                               acc[i][6] + bias, acc[i][7] + bias);
    }
}

// Pad kernels keep halo_attn_k in the ncu capture slot (#4).
__global__ void pad_k() {}

// =====================================================================
extern "C" void kernel_launch(void* const* d_in, const int* in_sizes, int n_in,
                              void* d_out, int out_size)
{
    const float* x   = (const float*)d_in[0];
    const float* wq  = (const float*)d_in[1];
    const float* wkv = (const float*)d_in[2];
    const float* fcw = (const float*)d_in[3];
    const float* fcb = (const float*)d_in[4];
    const float* rh  = (const float*)d_in[5];
    const float* rw  = (const float*)d_in[6];
    float* out = (float*)d_out;

    cudaFuncSetAttribute(halo_attn_k,
                         cudaFuncAttributeMaxDynamicSharedMemorySize, SMEMB_);

    pad_k<<<1, 32>>>();
    pad_k<<<1, 32>>>();
    qkv_gemm_k<<<dim3(P_ / 128, 6, B_), 256>>>(x, wq, wkv);
    halo_attn_k<<<dim3(NB_, B_), 512, SMEMB_>>>(rh, rw);
    fc_gemm_k<<<dim3(P_ / 128, C_ / 64, B_), 256>>>(fcw, fcb, out);
}

// round 17
// speedup vs baseline: 2.8278x; 1.3787x over previous
#include <cuda_runtime.h>
#include <cuda_fp16.h>
#include <cstdint>

// ---------------- problem constants ----------------
#define B_     4
#define C_     256
#define H_     128
#define W_     128
#define P_     (H_ * W_)      // 16384 pixels per batch
#define HEADS_ 8
#define HALO_  3
#define NKEY_  196
#define NB_    256
#define ROWF_  384            // g_qkv row: 768 halves (q|k|v fp16) = 384 floats

// ---------------- scratch (device globals) ----------------
__device__ float g_qkv[(size_t)B_ * P_ * ROWF_];  // [b][p]: q|k|v all fp16
__device__ float g_ctx[(size_t)B_ * P_ * C_];     // [b][p][c] pixel-major fp32

// ---------------- mma / ldmatrix helpers ----------------
#define LDM_X4(A0,A1,A2,A3,ADDR)                                               \
    asm volatile("ldmatrix.sync.aligned.m8n8.x4.shared.b16 {%0,%1,%2,%3},[%4];"\
                 : "=r"(A0),"=r"(A1),"=r"(A2),"=r"(A3) : "r"(ADDR))
#define LDM_X2(B0,B1,ADDR)                                                     \
    asm volatile("ldmatrix.sync.aligned.m8n8.x2.shared.b16 {%0,%1},[%2];"      \
                 : "=r"(B0),"=r"(B1) : "r"(ADDR))
#define LDM_X2T(B0,B1,ADDR)                                                    \
    asm volatile("ldmatrix.sync.aligned.m8n8.x2.trans.shared.b16 {%0,%1},[%2];"\
                 : "=r"(B0),"=r"(B1) : "r"(ADDR))
#define MMA16816(C0,C1,C2,C3,A0,A1,A2,A3,B0,B1)                                \
    asm volatile("mma.sync.aligned.m16n8k16.row.col.f32.f16.f16.f32 "          \
                 "{%0,%1,%2,%3},{%4,%5,%6,%7},{%8,%9},{%0,%1,%2,%3};"          \
                 : "+f"(C0),"+f"(C1),"+f"(C2),"+f"(C3)                         \
                 : "r"(A0),"r"(A1),"r"(A2),"r"(A3),"r"(B0),"r"(B1))
#define MMA_TF32(C,A,Bv)                                                       \
    asm volatile("mma.sync.aligned.m16n8k8.row.col.f32.tf32.tf32.f32 "         \
                 "{%0,%1,%2,%3},{%4,%5,%6,%7},{%8,%9},{%0,%1,%2,%3};"          \
                 : "+f"((C)[0]),"+f"((C)[1]),"+f"((C)[2]),"+f"((C)[3])         \
                 : "r"((A)[0]),"r"((A)[1]),"r"((A)[2]),"r"((A)[3]),            \
                   "r"((Bv)[0]),"r"((Bv)[1]))

__device__ __forceinline__ float tf32r(float x) {
    uint32_t u;
    asm("cvt.rna.tf32.f32 %0, %1;" : "=r"(u) : "f"(x));
    return __uint_as_float(u);
}

// =====================================================================
// Kernel 1: QKV projection via tf32 tensor-core MMA.
// out[p][o] = sum_c x[c][p] * W[o][c]; outputs fp16.
// CTA 128p x 128o, 8 warps (2m x 4n), warp 64x32, BK=16 ping-pong.
// =====================================================================
#define QST_ 136   // smem row stride (floats): frag banks (8k+m)%32 distinct

__global__ __launch_bounds__(256) void qkv_gemm_k(
    const float* __restrict__ x,
    const float* __restrict__ wq,
    const float* __restrict__ wkv)
{
    __shared__ float As[2][16][QST_];   // [k][m=p]
    __shared__ float Bs[2][16][QST_];   // [k][n=o]

    const int pT  = blockIdx.x * 128;
    const int oT  = blockIdx.y * 128;
    const int b   = blockIdx.z;
    const int tid = threadIdx.x;
    const int w   = tid >> 5;
    const int lane = tid & 31;
    const int mbase = (w & 1) * 64;
    const int nbase = (w >> 1) * 32;

    const float* xb = x + (size_t)b * C_ * P_;

    // staging indices
    const int ka0 = tid >> 5;             // A rows ka0, ka0+8
    const int ma4 = (tid & 31) << 2;
    const int ol0 = tid >> 2;             // B cols ol0, ol0+64
    const int ol1 = ol0 + 64;
    const int k4  = (tid & 3) << 2;
    const int or0 = oT + ol0;
    const int or1 = oT + ol1;
    const float* wr0 = (or0 < 256) ? (wq + or0 * 256) : (wkv + (or0 - 256) * 256);
    const float* wr1 = (or1 < 256) ? (wq + or1 * 256) : (wkv + (or1 - 256) * 256);

    float acc[4][4][4];
#pragma unroll
    for (int mf = 0; mf < 4; mf++)
#pragma unroll
        for (int nf = 0; nf < 4; nf++)
#pragma unroll
            for (int i = 0; i < 4; i++) acc[mf][nf][i] = 0.f;

    float4 ra0, ra1, rb0, rb1;

#define QKV_LOADG(K0)                                                          \
    {                                                                          \
        ra0 = *(const float4*)&xb[(size_t)((K0) + ka0) * P_ + pT + ma4];       \
        ra1 = *(const float4*)&xb[(size_t)((K0) + 8 + ka0) * P_ + pT + ma4];   \
        rb0 = *(const float4*)&wr0[(K0) + k4];                                 \
        rb1 = *(const float4*)&wr1[(K0) + k4];                                 \
    }
#define QKV_STORE(BUF)                                                         \
    {                                                                          \
        float4 ta0 = make_float4(tf32r(ra0.x), tf32r(ra0.y),                   \
                                 tf32r(ra0.z), tf32r(ra0.w));                  \
        float4 ta1 = make_float4(tf32r(ra1.x), tf32r(ra1.y),                   \
                                 tf32r(ra1.z), tf32r(ra1.w));                  \
        *(float4*)&As[BUF][ka0][ma4]     = ta0;                                \
        *(float4*)&As[BUF][8 + ka0][ma4] = ta1;                                \
        Bs[BUF][k4 + 0][ol0] = tf32r(rb0.x); Bs[BUF][k4 + 1][ol0] = tf32r(rb0.y); \
        Bs[BUF][k4 + 2][ol0] = tf32r(rb0.z); Bs[BUF][k4 + 3][ol0] = tf32r(rb0.w); \
        Bs[BUF][k4 + 0][ol1] = tf32r(rb1.x); Bs[BUF][k4 + 1][ol1] = tf32r(rb1.y); \
        Bs[BUF][k4 + 2][ol1] = tf32r(rb1.z); Bs[BUF][k4 + 3][ol1] = tf32r(rb1.w); \
    }

    QKV_LOADG(0);
    QKV_STORE(0);
    __syncthreads();

    const int arow = lane >> 2;    // 0..7
    const int acol = lane & 3;     // 0..3

    for (int it = 0; it < 16; it++) {
        const int buf = it & 1;
        if (it < 15) QKV_LOADG((it + 1) * 16);
#pragma unroll
        for (int ks = 0; ks < 16; ks += 8) {
            uint32_t afr[4][4];
#pragma unroll
            for (int mf = 0; mf < 4; mf++) {
                int m = mbase + mf * 16 + arow;
                afr[mf][0] = __float_as_uint(As[buf][ks + acol][m]);
                afr[mf][1] = __float_as_uint(As[buf][ks + acol][m + 8]);
                afr[mf][2] = __float_as_uint(As[buf][ks + 4 + acol][m]);
                afr[mf][3] = __float_as_uint(As[buf][ks + 4 + acol][m + 8]);
            }
#pragma unroll
            for (int nf = 0; nf < 4; nf++) {
                uint32_t bfr[2];
                int n = nbase + nf * 8 + arow;
                bfr[0] = __float_as_uint(Bs[buf][ks + acol][n]);
                bfr[1] = __float_as_uint(Bs[buf][ks + 4 + acol][n]);
#pragma unroll
                for (int mf = 0; mf < 4; mf++)
                    MMA_TF32(acc[mf][nf], afr[mf], bfr);
            }
        }
        if (it < 15) {
            QKV_STORE(buf ^ 1);
            __syncthreads();
        }
    }

    // epilogue: fp16 stores (c0,c1)->(m,n..n+1), (c2,c3)->(m+8,...)
#pragma unroll
    for (int mf = 0; mf < 4; mf++) {
        int m = mbase + mf * 16 + arow;
        __half* r0 = (__half*)&g_qkv[(size_t)((size_t)b * P_ + pT + m) * ROWF_];
        __half* r1 = (__half*)&g_qkv[(size_t)((size_t)b * P_ + pT + m + 8) * ROWF_];
#pragma unroll
        for (int nf = 0; nf < 4; nf++) {
            int o = oT + nbase + nf * 8 + acol * 2;
            *(__half2*)&r0[o] = __floats2half2_rn(acc[mf][nf][0], acc[mf][nf][1]);
            *(__half2*)&r1[o] = __floats2half2_rn(acc[mf][nf][2], acc[mf][nf][3]);
        }
    }
}

// =====================================================================
// Kernel 2: halo attention via tensor cores (mma.sync m16n8k16).
// 64 q/CTA, 512 threads, 2 CTAs/SM. Q/K/V/P fp16, accum fp32.
// Rel tables stored TRANSPOSED [d][t] (stride 28) -> conflict-free bias.
// =====================================================================
// smem byte offsets (16B aligned)
#define SB_K_   0                    // 224 x 40 halves (80B rows) = 17920
#define SB_V_   17920                // 17920
#define SB_Q_   35840                // 64 x 40 halves = 5120
#define SB_P_   40960                // 64 x 232 halves (464B rows) = 29696
#define SB_BW_  70656                // 64x14 f32 = 3584
#define SB_BH_  74240                // 3584
#define SB_M_   77824                // 64x4 f32 = 1024
#define SB_L_   78848                // 1024
#define SB_RH_  79872                // 32x28 f32 transposed = 3584
#define SB_RW_  83456                // 3584
#define SMEMB_  87040

__global__ __launch_bounds__(512, 2) void halo_attn_k(
    const float* __restrict__ rel_h,
    const float* __restrict__ rel_w)
{
    extern __shared__ char smem[];
    const uint32_t sb = (uint32_t)__cvta_generic_to_shared(smem);

    float* sBW = (float*)(smem + SB_BW_);
    float* sBH = (float*)(smem + SB_BH_);
    float* sM  = (float*)(smem + SB_M_);
    float* sL  = (float*)(smem + SB_L_);
    float* sRH = (float*)(smem + SB_RH_);   // [d][t] stride 28
    float* sRW = (float*)(smem + SB_RW_);   // [d][t] stride 28

    const int b    = blockIdx.y;
    const int blk  = blockIdx.x;
    const int bh   = blk >> 4;
    const int bw   = blk & 15;
    const int tid  = threadIdx.x;
    const int w    = tid >> 5;
    const int lane = tid & 31;
    const int kt   = w & 3;            // n-chunk (score) / d-tile (ctx)
    const int qb   = (w >> 2) * 16;    // m-tile base row
    const int cb   = kt * 56;          // score col base
    const float scale = 0.1767766952966369f;   // 1/sqrt(32)

    const char* gb = (const char*)g_qkv + (size_t)b * P_ * 1536;

    // stage rel tables TRANSPOSED; zero K/V pad rows [196,224)
    for (int i = tid; i < 27 * 32; i += 512) {
        int t = i >> 5, d = i & 31;          // input layout [t][d]
        sRH[d * 28 + t] = rel_h[i];
        sRW[d * 28 + t] = rel_w[i];
    }
    if (tid < 280) {
        int arr = tid / 140, rr = tid % 140;
        int r = 196 + rr / 5, c5 = rr % 5;
        *(uint4*)(smem + (arr ? SB_V_ : SB_K_) + r * 80 + c5 * 16) =
            make_uint4(0, 0, 0, 0);
    }

    for (int hd = 0; hd < HEADS_; hd++) {
        __syncthreads();   // smem reuse guard (and init)

        // ---- load Q: 64 rows x 64B (fp16) ----
        if (tid < 256) {
            int r = tid >> 2, c = tid & 3;
            int p = (bh * 8 + (r >> 3)) * 128 + bw * 8 + (r & 7);
            uint4 u = *(const uint4*)(gb + (size_t)p * 1536 + hd * 64 + c * 16);
            *(uint4*)(smem + SB_Q_ + r * 80 + c * 16) = u;
        }
        // ---- load K,V: 196 rows x 64B each, zero-pad halo ----
        for (int idx = tid; idx < 1568; idx += 512) {
            int r = idx >> 3, rem = idx & 7;
            int arr = rem >> 2, c = rem & 3;
            int iw = r / 14, jw = r - iw * 14;
            int hp = bh * 8 - HALO_ + iw;
            int wp = bw * 8 - HALO_ + jw;
            uint4 u = make_uint4(0, 0, 0, 0);
            if (hp >= 0 && hp < H_ && wp >= 0 && wp < W_)
                u = *(const uint4*)(gb + (size_t)(hp * 128 + wp) * 1536
                                    + 512 + arr * 512 + hd * 64 + c * 16);
            *(uint4*)(smem + (arr ? SB_V_ : SB_K_) + r * 80 + c * 16) = u;
        }
        __syncthreads();

        // ---- rel-pos bias tables (conflict-free transposed reads) ----
        for (int idx = tid; idx < 64 * 14; idx += 512) {
            int qi = idx / 14, j = idx - qi * 14;
            int xq = qi >> 3, yq = qi & 7;
            int jw = j - yq + 13;
            int jh = j - xq + 13;
            const __half2* q2p = (const __half2*)(smem + SB_Q_ + qi * 80);
            float aw = 0.f, ah = 0.f;
#pragma unroll
            for (int d2 = 0; d2 < 16; d2++) {
                float2 q = __half22float2(q2p[d2]);
                aw += q.x * sRW[(2 * d2) * 28 + jw] + q.y * sRW[(2 * d2 + 1) * 28 + jw];
                ah += q.x * sRH[(2 * d2) * 28 + jh] + q.y * sRH[(2 * d2 + 1) * 28 + jh];
            }
            sBW[idx] = aw;
            sBH[idx] = ah;
        }
        __syncthreads();

        // ---- score mma: warp covers rows [qb,qb+16) x cols [cb,cb+56) ----
        float c[7][4];
#pragma unroll
        for (int nt = 0; nt < 7; nt++)
#pragma unroll
            for (int i = 0; i < 4; i++) c[nt][i] = 0.f;
        {
            const uint32_t aBase = sb + SB_Q_
                + (qb + (lane & 7) + ((lane >> 3) & 1) * 8) * 80
                + ((lane >> 4) & 1) * 16;
            const uint32_t bRow = cb + (lane & 7);
            const uint32_t bSel = ((lane >> 3) & 1) * 16;
#pragma unroll
            for (int kk = 0; kk < 2; kk++) {
                uint32_t a0, a1, a2, a3;
                LDM_X4(a0, a1, a2, a3, aBase + kk * 32);
#pragma unroll
                for (int nt = 0; nt < 7; nt++) {
                    uint32_t b0, b1;
                    LDM_X2(b0, b1, sb + SB_K_ + (bRow + nt * 8) * 80 + bSel + kk * 32);
                    MMA16816(c[nt][0], c[nt][1], c[nt][2], c[nt][3],
                             a0, a1, a2, a3, b0, b1);
                }
            }
        }

        // ---- epilogue: scale + bias + row max ----
        const int r1 = qb + (lane >> 2);
        const int r2 = r1 + 8;
        float m1 = -1e30f, m2 = -1e30f;
#pragma unroll
        for (int nt = 0; nt < 7; nt++) {
            int col = cb + nt * 8 + 2 * (lane & 3);
            if (col < NKEY_) {
                int dv0 = col / 14,        cm0 = col - dv0 * 14;
                int dv1 = (col + 1) / 14,  cm1 = (col + 1) - dv1 * 14;
                float s0 = c[nt][0] * scale + sBW[r1 * 14 + cm0] + sBH[r1 * 14 + dv0];
                float s1 = c[nt][1] * scale + sBW[r1 * 14 + cm1] + sBH[r1 * 14 + dv1];
                float s2 = c[nt][2] * scale + sBW[r2 * 14 + cm0] + sBH[r2 * 14 + dv0];
                float s3 = c[nt][3] * scale + sBW[r2 * 14 + cm1] + sBH[r2 * 14 + dv1];
                c[nt][0] = s0; c[nt][1] = s1; c[nt][2] = s2; c[nt][3] = s3;
                m1 = fmaxf(m1, fmaxf(s0, s1));
                m2 = fmaxf(m2, fmaxf(s2, s3));
            } else {
                c[nt][0] = c[nt][1] = c[nt][2] = c[nt][3] = -1e30f;
            }
        }
        m1 = fmaxf(m1, __shfl_xor_sync(0xffffffffu, m1, 1));
        m1 = fmaxf(m1, __shfl_xor_sync(0xffffffffu, m1, 2));
        m2 = fmaxf(m2, __shfl_xor_sync(0xffffffffu, m2, 1));
        m2 = fmaxf(m2, __shfl_xor_sync(0xffffffffu, m2, 2));
        if ((lane & 3) == 0) {
            sM[r1 * 4 + kt] = m1;
            sM[r2 * 4 + kt] = m2;
        }
        __syncthreads();

        // ---- exp + fp16 prob store + partial sums ----
        float M1, M2;
        {
            const float* mp1 = sM + r1 * 4;
            const float* mp2 = sM + r2 * 4;
            M1 = fmaxf(fmaxf(mp1[0], mp1[1]), fmaxf(mp1[2], mp1[3]));
            M2 = fmaxf(fmaxf(mp2[0], mp2[1]), fmaxf(mp2[2], mp2[3]));
        }
        float s1 = 0.f, s2 = 0.f;
#pragma unroll
        for (int nt = 0; nt < 7; nt++) {
            int col = cb + nt * 8 + 2 * (lane & 3);
            __half2 h1, h2;
            if (col < NKEY_) {
                float e0 = __expf(c[nt][0] - M1);
                float e1 = __expf(c[nt][1] - M1);
                float e2 = __expf(c[nt][2] - M2);
                float e3 = __expf(c[nt][3] - M2);
                s1 += e0 + e1;
                s2 += e2 + e3;
                h1 = __floats2half2_rn(e0, e1);
                h2 = __floats2half2_rn(e2, e3);
            } else {
                h1 = __floats2half2_rn(0.f, 0.f);
                h2 = h1;
            }
            *(__half2*)(smem + SB_P_ + r1 * 464 + col * 2) = h1;
            *(__half2*)(smem + SB_P_ + r2 * 464 + col * 2) = h2;
        }
        s1 += __shfl_xor_sync(0xffffffffu, s1, 1);
        s1 += __shfl_xor_sync(0xffffffffu, s1, 2);
        s2 += __shfl_xor_sync(0xffffffffu, s2, 1);
        s2 += __shfl_xor_sync(0xffffffffu, s2, 2);
        if ((lane & 3) == 0) {
            sL[r1 * 4 + kt] = s1;
            sL[r2 * 4 + kt] = s2;
        }
        __syncthreads();

        // ---- ctx mma: O[qb..qb+16) x d-tile kt*8 over 224 keys ----
        float o0 = 0.f, o1 = 0.f, o2 = 0.f, o3 = 0.f;
        {
            const uint32_t aP = sb + SB_P_
                + (qb + (lane & 7) + ((lane >> 3) & 1) * 8) * 464
                + ((lane >> 4) & 1) * 16;
            const uint32_t vCol = (uint32_t)kt * 16;   // d0*2 bytes
#pragma unroll
            for (int kk = 0; kk < 14; kk++) {
                uint32_t a0, a1, a2, a3, b0, b1;
                LDM_X4(a0, a1, a2, a3, aP + kk * 32);
                uint32_t vRow = kk * 16 + (lane & 7) + ((lane >> 3) & 1) * 8;
                LDM_X2T(b0, b1, sb + SB_V_ + vRow * 80 + vCol);
                MMA16816(o0, o1, o2, o3, a0, a1, a2, a3, b0, b1);
            }
        }
        // ---- normalize + store ----
        {
            const float* lp1 = sL + r1 * 4;
            const float* lp2 = sL + r2 * 4;
            float inv1 = 1.f / (lp1[0] + lp1[1] + lp1[2] + lp1[3]);
            float inv2 = 1.f / (lp2[0] + lp2[1] + lp2[2] + lp2[3]);
            int dc = kt * 8 + 2 * (lane & 3);
            int p1 = (bh * 8 + (r1 >> 3)) * 128 + bw * 8 + (r1 & 7);
            int p2 = (bh * 8 + (r2 >> 3)) * 128 + bw * 8 + (r2 & 7);
            *(float2*)&g_ctx[((size_t)b * P_ + p1) * C_ + hd * 32 + dc] =
                make_float2(o0 * inv1, o1 * inv1);
            *(float2*)&g_ctx[((size_t)b * P_ + p2) * C_ + hd * 32 + dc] =
                make_float2(o2 * inv2, o3 * inv2);
        }
    }
}

// =====================================================================
// Kernel 3: FC epilogue, ping-pong, reads pixel-major ctx.
// =====================================================================
#define BSTRIDE_ 132

__global__ __launch_bounds__(256) void fc_gemm_k(
    const float* __restrict__ fcw,
    const float* __restrict__ fcb,
    float* __restrict__ out)
{
    __shared__ float As[2][16][64];
    __shared__ float Bs[2][16][BSTRIDE_];

    const int pT  = blockIdx.x * 128;
    const int oT  = blockIdx.y * 64;
    const int b   = blockIdx.z;
    const int tid = threadIdx.x;
    const int m0  = (tid >> 4) * 4;
    const int n0  = (tid & 15) * 4;

    const int am = tid & 63;
    const int ak = (tid >> 6) * 4;
    const int pl = tid >> 1;
    const int cg = (tid & 1) * 4;
    const float* arow = fcw + (oT + am) * 256;
    const float* ctxb = g_ctx + ((size_t)b * P_ + pT) * C_;

    float acc[4][8];
#pragma unroll
    for (int i = 0; i < 4; i++)
#pragma unroll
        for (int j = 0; j < 8; j++) acc[i][j] = 0.f;

    float4 ra, rb0, rb1;

#define FC_LOADG(K0)                                                           \
    {                                                                          \
        ra  = *(const float4*)&arow[(K0) + ak];                                \
        rb0 = *(const float4*)&ctxb[(size_t)pl * C_ + (K0) + cg];              \
        rb1 = *(const float4*)&ctxb[(size_t)pl * C_ + (K0) + 8 + cg];          \
    }
#define FC_STORE(BUF)                                                          \
    {                                                                          \
        As[BUF][ak + 0][am] = ra.x; As[BUF][ak + 1][am] = ra.y;                \
        As[BUF][ak + 2][am] = ra.z; As[BUF][ak + 3][am] = ra.w;                \
        Bs[BUF][cg + 0][pl] = rb0.x; Bs[BUF][cg + 1][pl] = rb0.y;              \
        Bs[BUF][cg + 2][pl] = rb0.z; Bs[BUF][cg + 3][pl] = rb0.w;              \
        Bs[BUF][8 + cg + 0][pl] = rb1.x; Bs[BUF][8 + cg + 1][pl] = rb1.y;      \
        Bs[BUF][8 + cg + 2][pl] = rb1.z; Bs[BUF][8 + cg + 3][pl] = rb1.w;      \
    }

    FC_LOADG(0);
    FC_STORE(0);
    __syncthreads();

    for (int it = 0; it < 16; it++) {
        const int buf = it & 1;
        if (it < 15) FC_LOADG((it + 1) * 16);
#pragma unroll
        for (int kk = 0; kk < 16; kk++) {
            float4 av = *(float4*)&As[buf][kk][m0];
            float4 b0 = *(float4*)&Bs[buf][kk][n0];
            float4 b1 = *(float4*)&Bs[buf][kk][n0 + 64];
            float a[4] = {av.x, av.y, av.z, av.w};
            float bb[8] = {b0.x, b0.y, b0.z, b0.w, b1.x, b1.y, b1.z, b1.w};
#pragma unroll
            for (int i = 0; i < 4; i++)
#pragma unroll
                for (int j = 0; j < 8; j++) acc[i][j] += a[i] * bb[j];
        }
        if (it < 15) {
            FC_STORE(buf ^ 1);
            __syncthreads();
        }
    }

#pragma unroll
    for (int i = 0; i < 4; i++) {
        int o = oT + m0 + i;
        float bias = fcb[o];
        float* orow = out + ((size_t)b * C_ + o) * P_ + pT;
        *(float4*)&orow[n0]      = make_float4(acc[i][0] + bias, acc[i][1] + bias,
                                               acc[i][2] + bias, acc[i][3] + bias);
        *(float4*)&orow[n0 + 64] = make_float4(acc[i][4] + bias, acc[i][5] + bias,
                                               acc[i][6] + bias, acc[i][7] + bias);
    }
}

// Pad kernels: 3 pads put the NEW qkv_gemm_k in ncu capture slot #4.
__global__ void pad_k() {}

// =====================================================================
extern "C" void kernel_launch(void* const* d_in, const int* in_sizes, int n_in,
                              void* d_out, int out_size)
{
    const float* x   = (const float*)d_in[0];
    const float* wq  = (const float*)d_in[1];
    const float* wkv = (const float*)d_in[2];
    const float* fcw = (const float*)d_in[3];
    const float* fcb = (const float*)d_in[4];
    const float* rh  = (const float*)d_in[5];
    const float* rw  = (const float*)d_in[6];
    float* out = (float*)d_out;

    cudaFuncSetAttribute(halo_attn_k,
                         cudaFuncAttributeMaxDynamicSharedMemorySize, SMEMB_);

    pad_k<<<1, 32>>>();
    pad_k<<<1, 32>>>();
    pad_k<<<1, 32>>>();
    qkv_gemm_k<<<dim3(P_ / 128, 6, B_), 256>>>(x, wq, wkv);
    halo_attn_k<<<dim3(NB_, B_), 512, SMEMB_>>>(rh, rw);
    fc_gemm_k<<<dim3(P_ / 128, C_ / 64, B_), 256>>>(fcw, fcb, out);
}